// round 13
// baseline (speedup 1.0000x reference)
#include <cuda_runtime.h>
#include <cuda_fp16.h>
#include <cstdint>

#define BB   16
#define NN   1024
#define INF  256
#define HH   4
#define NEG_SLOPE 0.2f

// attn smem geometry: i-tile 64, j-tile 32, 2 CTAs/SM
#define SROW   80                 // 32 j * 2B + 16B pad (phase-conflict-free: stride 5x16B)
#define SHEAD  (64 * SROW)        // 5120
#define S_BYTES (4 * SHEAD)       // 20480
#define HROW   528                // 256 c * 2B + 16B pad
#define HTILE  (32 * HROW)        // 16896 per H buffer
#define DYN_BYTES (S_BYTES + 2 * HTILE)   // 54272

// hgemm smem geometry: 128m x 128n block, k-chunk 64, double buffered
#define AROWG  144
#define ABUF   (128 * AROWG)      // 18432
#define BROWG  272
#define BBUF   (64 * BROWG)       // 17408
#define GEMM_DYN (2 * (ABUF + BBUF))   // 71680

// ---- scratch ----
__device__ __half g_xh[BB * NN * 256];     // fp16 x
__device__ __half g_Wh[256 * 256];         // fp16 W
__device__ float  g_Wa[256 * 8];           // W @ [a_src|a_dst]
__device__ __half g_hh[BB * NN * 256];     // fp16 h
__device__ float  g_ssrc[BB * NN * HH];
__device__ float  g_sdst[BB * NN * HH];
#define NEG16 -1e30f,-1e30f,-1e30f,-1e30f,-1e30f,-1e30f,-1e30f,-1e30f,\
              -1e30f,-1e30f,-1e30f,-1e30f,-1e30f,-1e30f,-1e30f,-1e30f
__device__ float  g_mx[BB * HH] = { NEG16, NEG16, NEG16, NEG16 };

// ---- helpers ----
__device__ __forceinline__ uint32_t smem_u32(const void* p) {
    uint32_t a;
    asm("{ .reg .u64 t; cvta.to.shared.u64 t, %1; cvt.u32.u64 %0, t; }" : "=r"(a) : "l"(p));
    return a;
}
__device__ __forceinline__ void ldsm_x4(uint32_t* d, uint32_t addr) {
    asm volatile("ldmatrix.sync.aligned.m8n8.x4.shared.b16 {%0,%1,%2,%3}, [%4];"
        : "=r"(d[0]), "=r"(d[1]), "=r"(d[2]), "=r"(d[3]) : "r"(addr));
}
__device__ __forceinline__ void ldsm_x4t(uint32_t* d, uint32_t addr) {
    asm volatile("ldmatrix.sync.aligned.m8n8.x4.trans.shared.b16 {%0,%1,%2,%3}, [%4];"
        : "=r"(d[0]), "=r"(d[1]), "=r"(d[2]), "=r"(d[3]) : "r"(addr));
}
__device__ __forceinline__ void mma16816(float* c, const uint32_t* a, uint32_t b0, uint32_t b1) {
    asm volatile("mma.sync.aligned.m16n8k16.row.col.f32.f16.f16.f32 "
        "{%0,%1,%2,%3}, {%4,%5,%6,%7}, {%8,%9}, {%0,%1,%2,%3};"
        : "+f"(c[0]), "+f"(c[1]), "+f"(c[2]), "+f"(c[3])
        : "r"(a[0]), "r"(a[1]), "r"(a[2]), "r"(a[3]), "r"(b0), "r"(b1));
}
#define CP_ASYNC16(smem, gptr) \
    asm volatile("cp.async.cg.shared.global [%0], [%1], 16;" :: "r"(smem), "l"(gptr) : "memory")
#define CP_COMMIT() asm volatile("cp.async.commit_group;" ::: "memory")
#define CP_WAIT1()  asm volatile("cp.async.wait_group 1;" ::: "memory")
#define CP_WAIT0()  asm volatile("cp.async.wait_group 0;" ::: "memory")

__device__ __forceinline__ void atomicMaxFloat(float* a, float v) {
    if (v >= 0.f) atomicMax((int*)a, __float_as_int(v));
    else          atomicMin((unsigned int*)a, __float_as_uint(v));
}

// ============================================================
// [0] fused: W -> fp16 (blocks 0..63) + Wa = W @ [a_src|a_dst] (blocks 64..71)
// ============================================================
__global__ __launch_bounds__(256) void prep0_kernel(const float* __restrict__ W,
                                                    const float* __restrict__ av)
{
    if (blockIdx.x < 64) {
        int i = (blockIdx.x * 256 + threadIdx.x) << 2;
        float4 v = *(const float4*)&W[i];
        __half2 h0 = __floats2half2_rn(v.x, v.y);
        __half2 h1 = __floats2half2_rn(v.z, v.w);
        *(uint2*)((unsigned short*)g_Wh + i) = make_uint2(*(uint32_t*)&h0, *(uint32_t*)&h1);
    } else {
        int c = blockIdx.x - 64;     // 0..7
        int h = c & 3;
        int dbase = (c >= 4) ? 64 : 0;
        int k = threadIdx.x;
        float p = 0.f;
        #pragma unroll 16
        for (int d = 0; d < 64; ++d)
            p = fmaf(W[k * 256 + h * 64 + d], av[(dbase + d) * 4 + h], p);
        g_Wa[k * 8 + c] = p;
    }
}

// ============================================================
// [1] scores s = x @ Wa (fp32, exact) + global max + x -> fp16
// ============================================================
__global__ __launch_bounds__(256) void score_kernel(const float* __restrict__ x)
{
    __shared__ float Wa_s[256 * 9];
    int t = threadIdx.x;
    for (int i = t; i < 2048; i += 256)
        Wa_s[(i >> 3) * 9 + (i & 7)] = g_Wa[i];
    __syncthreads();

    int row  = blockIdx.x * 8 + (t >> 5);
    int lane = t & 31;
    const float* xr = x + row * 256;

    float xv[8];
    #pragma unroll
    for (int u = 0; u < 8; ++u) xv[u] = xr[(u << 5) + lane];

    unsigned short* xo = (unsigned short*)g_xh + row * 256 + lane;
    #pragma unroll
    for (int u = 0; u < 8; ++u) {
        __half hv = __float2half_rn(xv[u]);
        xo[u << 5] = *(unsigned short*)&hv;
    }

    float s[8];
    #pragma unroll
    for (int c = 0; c < 8; ++c) {
        float p = 0.f;
        #pragma unroll
        for (int u = 0; u < 8; ++u)
            p = fmaf(xv[u], Wa_s[((u << 5) + lane) * 9 + c], p);
        #pragma unroll
        for (int o = 16; o; o >>= 1) p += __shfl_xor_sync(0xffffffffu, p, o);
        s[c] = p;
    }
    if (lane == 0) {
        int b = row >> 10;
        #pragma unroll
        for (int h = 0; h < 4; ++h) {
            g_ssrc[row * 4 + h] = s[h];
            g_sdst[row * 4 + h] = s[4 + h];
            atomicMaxFloat(&g_mx[b * 4 + h], s[4 + h]);
        }
    }
}

// ============================================================
// [2] h = x @ W via HMMA -> g_hh (unchanged from round 12)
// ============================================================
__global__ __launch_bounds__(256, 1)
void hgemm_kernel(float* __restrict__ dummy)
{
    extern __shared__ __align__(16) char sg[];
    const uint32_t sbA = smem_u32(sg);
    const uint32_t sbB = sbA + 2 * ABUF;

    const int t = threadIdx.x;
    const int lane = t & 31, w = t >> 5;
    const int nBase = blockIdx.x << 7;
    const int mBase = blockIdx.y << 7;

    const char* aSrc = (const char*)g_xh + (size_t)mBase * 512;
    const char* bSrc = (const char*)g_Wh + (size_t)nBase * 2;

    #pragma unroll
    for (int kc = 0; kc < 2; ++kc) {
        #pragma unroll
        for (int l = 0; l < 4; ++l) {
            int idx = t + (l << 8);
            CP_ASYNC16(sbA + kc * ABUF + (idx >> 3) * AROWG + ((idx & 7) << 4),
                       aSrc + (size_t)(idx >> 3) * 512 + kc * 128 + ((idx & 7) << 4));
        }
        #pragma unroll
        for (int l = 0; l < 4; ++l) {
            int idx = t + (l << 8);
            CP_ASYNC16(sbB + kc * BBUF + (idx >> 4) * BROWG + ((idx & 15) << 4),
                       bSrc + (size_t)(kc * 64 + (idx >> 4)) * 512 + ((idx & 15) << 4));
        }
        CP_COMMIT();
    }

    const int mw = w & 3, nw = w >> 2;
    const uint32_t aBase = sbA + ((mw << 5) + (lane & 15)) * AROWG + ((lane >> 4) << 4);
    const uint32_t bBase = sbB + (lane & 15) * BROWG + ((lane >> 4) << 4) + (nw << 7);

    float acc[2][8][4];
    #pragma unroll
    for (int f = 0; f < 2; ++f)
        #pragma unroll
        for (int n = 0; n < 8; ++n)
            #pragma unroll
            for (int c = 0; c < 4; ++c) acc[f][n][c] = 0.f;

    for (int kc = 0; kc < 4; ++kc) {
        if (kc + 2 < 4) { CP_WAIT1(); } else { CP_WAIT0(); }
        __syncthreads();
        const uint32_t aB = aBase + (kc & 1) * ABUF;
        const uint32_t bB = bBase + (kc & 1) * BBUF;
        #pragma unroll
        for (int ks = 0; ks < 4; ++ks) {
            uint32_t Af[2][4];
            ldsm_x4(Af[0], aB + (ks << 5));
            ldsm_x4(Af[1], aB + 16 * AROWG + (ks << 5));
            #pragma unroll
            for (int nn = 0; nn < 4; ++nn) {
                uint32_t Bf[4];
                ldsm_x4t(Bf, bB + ks * (16 * BROWG) + (nn << 5));
                mma16816(acc[0][2 * nn],     Af[0], Bf[0], Bf[1]);
                mma16816(acc[0][2 * nn + 1], Af[0], Bf[2], Bf[3]);
                mma16816(acc[1][2 * nn],     Af[1], Bf[0], Bf[1]);
                mma16816(acc[1][2 * nn + 1], Af[1], Bf[2], Bf[3]);
            }
        }
        __syncthreads();
        if (kc + 2 < 4) {
            int kn = kc + 2;
            #pragma unroll
            for (int l = 0; l < 4; ++l) {
                int idx = t + (l << 8);
                CP_ASYNC16(sbA + (kc & 1) * ABUF + (idx >> 3) * AROWG + ((idx & 7) << 4),
                           aSrc + (size_t)(idx >> 3) * 512 + kn * 128 + ((idx & 7) << 4));
            }
            #pragma unroll
            for (int l = 0; l < 4; ++l) {
                int idx = t + (l << 8);
                CP_ASYNC16(sbB + (kc & 1) * BBUF + (idx >> 4) * BROWG + ((idx & 15) << 4),
                           bSrc + (size_t)(kn * 64 + (idx >> 4)) * 512 + ((idx & 15) << 4));
            }
            CP_COMMIT();
        }
    }

    #pragma unroll
    for (int f = 0; f < 2; ++f) {
        int row0 = mBase + (mw << 5) + (f << 4) + (lane >> 2);
        #pragma unroll
        for (int n = 0; n < 8; ++n) {
            int col = nBase + (nw << 6) + (n << 3) + ((lane & 3) << 1);
            __half2 lo = __floats2half2_rn(acc[f][n][0], acc[f][n][1]);
            __half2 hi = __floats2half2_rn(acc[f][n][2], acc[f][n][3]);
            *(uint32_t*)((unsigned short*)g_hh + row0 * 256 + col)       = *(uint32_t*)&lo;
            *(uint32_t*)((unsigned short*)g_hh + (row0 + 8) * 256 + col) = *(uint32_t*)&hi;
        }
    }
    (void)dummy;
}

// ============================================================
// [3] HMMA attention aggregation, 2 CTAs/SM.
//     CTA = (b, 64-row i-tile), 256 thr / 8 warps, grid 256 (1 wave @ occ 2).
//     j-tile 32; S single-buffer, H double-buffered cp.async.
//     eA/eB/P/Q/R computed in-kernel (prep fused). Thread weight slice:
//     (row iw = t&63, 8-j chunk jc = t>>6).
// ============================================================
__global__ __launch_bounds__(256, 2)
void attn_mma_kernel(const int* __restrict__ adj, float* __restrict__ out)
{
    extern __shared__ __align__(16) char sb[];
    const uint32_t sbS = smem_u32(sb);
    const uint32_t sbH = sbS + S_BYTES;

    __shared__ float4 As_s[NN], Bs_s[NN];          // 32 KB (exp(sdst), exp(.2 sdst))
    __shared__ float4 den_part[4][64];             // 4 KB

    const int t = threadIdx.x;
    const int lane = t & 31, w = t >> 5;
    const int b  = blockIdx.x >> 4;
    const int i0 = (blockIdx.x & 15) << 6;

    // ---- prefetch H(0), H(1)
    const char* hsrc = (const char*)g_hh + ((size_t)(b << 10) << 9);
    #pragma unroll
    for (int kc = 0; kc < 2; ++kc) {
        #pragma unroll
        for (int l = 0; l < 4; ++l) {
            int idx = t + (l << 8);                // 0..1023 (32 rows x 32 chunks)
            CP_ASYNC16(sbH + kc * HTILE + (idx >> 5) * HROW + ((idx & 31) << 4),
                       hsrc + (size_t)kc * (32 * 512) + ((size_t)idx << 4));
        }
        CP_COMMIT();
    }

    // ---- fused prep: eA/eB for the whole batch row-space
    for (int k = t; k < NN; k += 256) {
        float4 sd = ((const float4*)g_sdst)[(b << 10) + k];
        As_s[k] = make_float4(__expf(sd.x), __expf(sd.y), __expf(sd.z), __expf(sd.w));
        Bs_s[k] = make_float4(__expf(NEG_SLOPE * sd.x), __expf(NEG_SLOPE * sd.y),
                              __expf(NEG_SLOPE * sd.z), __expf(NEG_SLOPE * sd.w));
    }

    // ---- per-row factors P/Q/R
    const int iw = t & 63;
    const int jc = t >> 6;
    float4 P4, Q4, R4;
    {
        float4 ss = ((const float4*)g_ssrc)[(b << 10) + i0 + iw];
        float4 mx = ((const float4*)g_mx)[b];
        float4 M;
        M.x = ss.x + mx.x; M.x = fmaxf(M.x, NEG_SLOPE * M.x);
        M.y = ss.y + mx.y; M.y = fmaxf(M.y, NEG_SLOPE * M.y);
        M.z = ss.z + mx.z; M.z = fmaxf(M.z, NEG_SLOPE * M.z);
        M.w = ss.w + mx.w; M.w = fmaxf(M.w, NEG_SLOPE * M.w);
        P4 = make_float4(__expf(ss.x - M.x), __expf(ss.y - M.y),
                         __expf(ss.z - M.z), __expf(ss.w - M.w));
        Q4 = make_float4(__expf(NEG_SLOPE * ss.x - M.x), __expf(NEG_SLOPE * ss.y - M.y),
                         __expf(NEG_SLOPE * ss.z - M.z), __expf(NEG_SLOPE * ss.w - M.w));
        R4 = make_float4(__expf(-ss.x), __expf(-ss.y), __expf(-ss.z), __expf(-ss.w));
    }
    const int4* arow = (const int4*)(adj + (((size_t)(b << 10) + i0 + iw) << 10));
    float d0 = 0.f, d1 = 0.f, d2 = 0.f, d3 = 0.f;

    // mma identity: head hg = w>>1, n32 chunk nc = w&1
    const int hg = w >> 1, nc = w & 1;
    const uint32_t aBase = sbS + hg * SHEAD + (lane & 15) * SROW + ((lane >> 4) << 4);
    const uint32_t bBase = sbH + (lane & 15) * HROW + ((lane >> 4) << 4)
                         + (hg << 7) + (nc << 6);

    float acc[4][4][4];
    #pragma unroll
    for (int mi = 0; mi < 4; ++mi)
        #pragma unroll
        for (int f = 0; f < 4; ++f)
            #pragma unroll
            for (int c = 0; c < 4; ++c) acc[mi][f][c] = 0.f;

    __syncthreads();                               // As_s/Bs_s ready

    // ---- weights S(0)
    {
        const int4 m0 = arow[jc << 1];
        const int4 m1 = arow[(jc << 1) + 1];
        const int mvi[8] = { m0.x, m0.y, m0.z, m0.w, m1.x, m1.y, m1.z, m1.w };
        uint32_t pk[4][4];
        float wl[4];
        #pragma unroll
        for (int pp = 0; pp < 8; ++pp) {
            int jl = (jc << 3) + pp;
            float4 A4 = As_s[jl];
            float4 B4 = Bs_s[jl];
            float msk = (mvi[pp] > 0) ? 1.f : 0.f;
            float w0 = msk * ((A4.x > R4.x) ? P4.x * A4.x : Q4.x * B4.x);
            float w1 = msk * ((A4.y > R4.y) ? P4.y * A4.y : Q4.y * B4.y);
            float w2 = msk * ((A4.z > R4.z) ? P4.z * A4.z : Q4.z * B4.z);
            float w3 = msk * ((A4.w > R4.w) ? P4.w * A4.w : Q4.w * B4.w);
            d0 += w0; d1 += w1; d2 += w2; d3 += w3;
            if (pp & 1) {
                __half2 p0 = __floats2half2_rn(wl[0], w0);
                __half2 p1 = __floats2half2_rn(wl[1], w1);
                __half2 p2 = __floats2half2_rn(wl[2], w2);
                __half2 p3 = __floats2half2_rn(wl[3], w3);
                pk[0][pp >> 1] = *(uint32_t*)&p0;
                pk[1][pp >> 1] = *(uint32_t*)&p1;
                pk[2][pp >> 1] = *(uint32_t*)&p2;
                pk[3][pp >> 1] = *(uint32_t*)&p3;
            } else { wl[0] = w0; wl[1] = w1; wl[2] = w2; wl[3] = w3; }
        }
        const uint32_t base = sbS + iw * SROW + (jc << 4);
        #pragma unroll
        for (int hh = 0; hh < 4; ++hh)
            asm volatile("st.shared.v4.b32 [%0], {%1,%2,%3,%4};"
                :: "r"(base + hh * SHEAD),
                   "r"(pk[hh][0]), "r"(pk[hh][1]), "r"(pk[hh][2]), "r"(pk[hh][3]) : "memory");
    }
    CP_WAIT1();                                    // H(0) arrived
    __syncthreads();

    for (int jt = 0; jt < 32; ++jt) {
        // ---- MMA on S, H buffer jt&1: 2 ks x (4 A-ldsm + 2 B-ldsm + 16 mma)
        {
            const uint32_t bB = bBase + (jt & 1) * HTILE;
            #pragma unroll
            for (int ks = 0; ks < 2; ++ks) {
                uint32_t Af[4][4];
                #pragma unroll
                for (int mi = 0; mi < 4; ++mi)
                    ldsm_x4(Af[mi], aBase + mi * (16 * SROW) + (ks << 5));
                #pragma unroll
                for (int nn = 0; nn < 2; ++nn) {
                    uint32_t Bf[4];
                    ldsm_x4t(Bf, bB + ks * (16 * HROW) + (nn << 5));
                    #pragma unroll
                    for (int mi = 0; mi < 4; ++mi) {
                        mma16816(acc[mi][2 * nn],     Af[mi], Bf[0], Bf[1]);
                        mma16816(acc[mi][2 * nn + 1], Af[mi], Bf[2], Bf[3]);
                    }
                }
            }
        }
        if (jt == 31) break;
        __syncthreads();                           // S/H reads done before overwrite

        // ---- prefetch H(jt+2) into buffer jt&1
        if (jt + 2 < 32) {
            const char* src = hsrc + (size_t)(jt + 2) * (32 * 512);
            const uint32_t dst = sbH + (jt & 1) * HTILE;
            #pragma unroll
            for (int l = 0; l < 4; ++l) {
                int idx = t + (l << 8);
                CP_ASYNC16(dst + (idx >> 5) * HROW + ((idx & 31) << 4),
                           src + ((size_t)idx << 4));
            }
            CP_COMMIT();
        }

        // ---- weights S(jt+1)
        {
            const int jn = jt + 1;
            const int j0 = jn << 5;
            const int4 m0 = arow[(jn << 3) + (jc << 1)];
            const int4 m1 = arow[(jn << 3) + (jc << 1) + 1];
            const int mvi[8] = { m0.x, m0.y, m0.z, m0.w, m1.x, m1.y, m1.z, m1.w };
            uint32_t pk[4][4];
            float wl[4];
            #pragma unroll
            for (int pp = 0; pp < 8; ++pp) {
                int jl = (jc << 3) + pp;
                float4 A4 = As_s[j0 + jl];
                float4 B4 = Bs_s[j0 + jl];
                float msk = (mvi[pp] > 0) ? 1.f : 0.f;
                float w0 = msk * ((A4.x > R4.x) ? P4.x * A4.x : Q4.x * B4.x);
                float w1 = msk * ((A4.y > R4.y) ? P4.y * A4.y : Q4.y * B4.y);
                float w2 = msk * ((A4.z > R4.z) ? P4.z * A4.z : Q4.z * B4.z);
                float w3 = msk * ((A4.w > R4.w) ? P4.w * A4.w : Q4.w * B4.w);
                d0 += w0; d1 += w1; d2 += w2; d3 += w3;
                if (pp & 1) {
                    __half2 p0 = __floats2half2_rn(wl[0], w0);
                    __half2 p1 = __floats2half2_rn(wl[1], w1);
                    __half2 p2 = __floats2half2_rn(wl[2], w2);
                    __half2 p3 = __floats2half2_rn(wl[3], w3);
                    pk[0][pp >> 1] = *(uint32_t*)&p0;
                    pk[1][pp >> 1] = *(uint32_t*)&p1;
                    pk[2][pp >> 1] = *(uint32_t*)&p2;
                    pk[3][pp >> 1] = *(uint32_t*)&p3;
                } else { wl[0] = w0; wl[1] = w1; wl[2] = w2; wl[3] = w3; }
            }
            const uint32_t base = sbS + iw * SROW + (jc << 4);
            #pragma unroll
            for (int hh = 0; hh < 4; ++hh)
                asm volatile("st.shared.v4.b32 [%0], {%1,%2,%3,%4};"
                    :: "r"(base + hh * SHEAD),
                       "r"(pk[hh][0]), "r"(pk[hh][1]), "r"(pk[hh][2]), "r"(pk[hh][3]) : "memory");
        }

        if (jt + 2 < 32) { CP_WAIT1(); } else { CP_WAIT0(); }   // H(jt+1) arrived
        __syncthreads();
    }

    // ---- denominator reduce + normalize + store
    den_part[jc][iw] = make_float4(d0, d1, d2, d3);
    __syncthreads();
    if (t < 64) {
        float4 a0 = den_part[0][t], a1 = den_part[1][t], a2 = den_part[2][t], a3 = den_part[3][t];
        den_part[0][t] = make_float4(a0.x + a1.x + a2.x + a3.x,
                                     a0.y + a1.y + a2.y + a3.y,
                                     a0.z + a1.z + a2.z + a3.z,
                                     a0.w + a1.w + a2.w + a3.w);
    }
    __syncthreads();

    const float* denf = (const float*)&den_part[0][0];
    #pragma unroll
    for (int mi = 0; mi < 4; ++mi) {
        const int row_lo = (mi << 4) + (lane >> 2);
        float dv0 = 1.f / denf[row_lo * 4 + hg];
        float dv1 = 1.f / denf[(row_lo + 8) * 4 + hg];
        #pragma unroll
        for (int f = 0; f < 4; ++f) {
            int col = (hg << 6) + (nc << 5) + (f << 3) + ((lane & 3) << 1);
            *(float2*)(out + ((b << 10) + i0 + row_lo) * 256 + col) =
                make_float2(acc[mi][f][0] * dv0, acc[mi][f][1] * dv0);
            *(float2*)(out + ((b << 10) + i0 + row_lo + 8) * 256 + col) =
                make_float2(acc[mi][f][2] * dv1, acc[mi][f][3] * dv1);
        }
    }
}

// ============================================================
extern "C" void kernel_launch(void* const* d_in, const int* in_sizes, int n_in,
                              void* d_out, int out_size)
{
    cudaFuncSetAttribute(attn_mma_kernel, cudaFuncAttributeMaxDynamicSharedMemorySize, DYN_BYTES);
    cudaFuncSetAttribute(hgemm_kernel, cudaFuncAttributeMaxDynamicSharedMemorySize, GEMM_DYN);

    const float* x = nullptr; const int* adj = nullptr;
    const float* W = nullptr; const float* a = nullptr;
    for (int i = 0; i < n_in; ++i) {
        int s = in_sizes[i];
        if      (s == BB * NN * INF) x   = (const float*)d_in[i];
        else if (s == BB * NN * NN)  adj = (const int*)d_in[i];
        else if (s == INF * HH * 64) W   = (const float*)d_in[i];
        else if (s == 2 * 64 * HH)   a   = (const float*)d_in[i];
    }

    prep0_kernel<<<72, 256>>>(W, a);                                   // idx 0
    score_kernel<<<2048, 256>>>(x);                                    // idx 1
    hgemm_kernel<<<dim3(2, 128), 256, GEMM_DYN>>>(nullptr);            // idx 2
    attn_mma_kernel<<<BB * (NN / 64), 256, DYN_BYTES>>>(adj, (float*)d_out);  // idx 3 -> profiled
}

// round 14
// speedup vs baseline: 1.0931x; 1.0931x over previous
#include <cuda_runtime.h>
#include <cuda_fp16.h>
#include <cstdint>

#define BB   16
#define NN   1024
#define INF  256
#define HH   4
#define NEG_SLOPE 0.2f

// attn smem: i-tile 64, j-tile 64; S double-buffered, H triple-buffered
#define SROW   144                // 64 j * 2B + 16B pad
#define SHEAD  (64 * SROW)        // 9216
#define S_BYTES (4 * SHEAD)       // 36864 per S buffer
#define HROW   528                // 256 c * 2B + 16B pad
#define HTILE  (64 * HROW)        // 33792 per H buffer
#define DYN_BYTES (2 * S_BYTES + 3 * HTILE)   // 175104

// hgemm smem: 128m x 128n block, k-chunk 64, double buffered
#define AROWG  144
#define ABUF   (128 * AROWG)      // 18432
#define BROWG  272
#define BBUF   (64 * BROWG)       // 17408
#define GEMM_DYN (2 * (ABUF + BBUF))   // 71680

// ---- scratch ----
__device__ __half g_xh[BB * NN * 256];
__device__ __half g_Wh[256 * 256];
__device__ float  g_Wa[256 * 8];
__device__ __half g_hh[BB * NN * 256];
__device__ float  g_ssrc[BB * NN * HH];
__device__ float  g_sdst[BB * NN * HH];
#define NEG16 -1e30f,-1e30f,-1e30f,-1e30f,-1e30f,-1e30f,-1e30f,-1e30f,\
              -1e30f,-1e30f,-1e30f,-1e30f,-1e30f,-1e30f,-1e30f,-1e30f
__device__ float  g_mx[BB * HH] = { NEG16, NEG16, NEG16, NEG16 };

// ---- helpers ----
__device__ __forceinline__ uint32_t smem_u32(const void* p) {
    uint32_t a;
    asm("{ .reg .u64 t; cvta.to.shared.u64 t, %1; cvt.u32.u64 %0, t; }" : "=r"(a) : "l"(p));
    return a;
}
__device__ __forceinline__ void ldsm_x4(uint32_t* d, uint32_t addr) {
    asm volatile("ldmatrix.sync.aligned.m8n8.x4.shared.b16 {%0,%1,%2,%3}, [%4];"
        : "=r"(d[0]), "=r"(d[1]), "=r"(d[2]), "=r"(d[3]) : "r"(addr));
}
__device__ __forceinline__ void ldsm_x4t(uint32_t* d, uint32_t addr) {
    asm volatile("ldmatrix.sync.aligned.m8n8.x4.trans.shared.b16 {%0,%1,%2,%3}, [%4];"
        : "=r"(d[0]), "=r"(d[1]), "=r"(d[2]), "=r"(d[3]) : "r"(addr));
}
__device__ __forceinline__ void mma16816(float* c, const uint32_t* a, uint32_t b0, uint32_t b1) {
    asm volatile("mma.sync.aligned.m16n8k16.row.col.f32.f16.f16.f32 "
        "{%0,%1,%2,%3}, {%4,%5,%6,%7}, {%8,%9}, {%0,%1,%2,%3};"
        : "+f"(c[0]), "+f"(c[1]), "+f"(c[2]), "+f"(c[3])
        : "r"(a[0]), "r"(a[1]), "r"(a[2]), "r"(a[3]), "r"(b0), "r"(b1));
}
#define CP_ASYNC16(smem, gptr) \
    asm volatile("cp.async.cg.shared.global [%0], [%1], 16;" :: "r"(smem), "l"(gptr) : "memory")
#define CP_COMMIT() asm volatile("cp.async.commit_group;" ::: "memory")
#define CP_WAIT1()  asm volatile("cp.async.wait_group 1;" ::: "memory")
#define CP_WAIT0()  asm volatile("cp.async.wait_group 0;" ::: "memory")

__device__ __forceinline__ void atomicMaxFloat(float* a, float v) {
    if (v >= 0.f) atomicMax((int*)a, __float_as_int(v));
    else          atomicMin((unsigned int*)a, __float_as_uint(v));
}

// ============================================================
// [0] fused: W -> fp16 (blocks 0..63) + Wa = W @ [a_src|a_dst] (blocks 64..71)
// ============================================================
__global__ __launch_bounds__(256) void prep0_kernel(const float* __restrict__ W,
                                                    const float* __restrict__ av)
{
    if (blockIdx.x < 64) {
        int i = (blockIdx.x * 256 + threadIdx.x) << 2;
        float4 v = *(const float4*)&W[i];
        __half2 h0 = __floats2half2_rn(v.x, v.y);
        __half2 h1 = __floats2half2_rn(v.z, v.w);
        *(uint2*)((unsigned short*)g_Wh + i) = make_uint2(*(uint32_t*)&h0, *(uint32_t*)&h1);
    } else {
        int c = blockIdx.x - 64;
        int h = c & 3;
        int dbase = (c >= 4) ? 64 : 0;
        int k = threadIdx.x;
        float p = 0.f;
        #pragma unroll 16
        for (int d = 0; d < 64; ++d)
            p = fmaf(W[k * 256 + h * 64 + d], av[(dbase + d) * 4 + h], p);
        g_Wa[k * 8 + c] = p;
    }
}

// ============================================================
// [1] scores s = x @ Wa (fp32, exact) + global max + x -> fp16
// ============================================================
__global__ __launch_bounds__(256) void score_kernel(const float* __restrict__ x)
{
    __shared__ float Wa_s[256 * 9];
    int t = threadIdx.x;
    for (int i = t; i < 2048; i += 256)
        Wa_s[(i >> 3) * 9 + (i & 7)] = g_Wa[i];
    __syncthreads();

    int row  = blockIdx.x * 8 + (t >> 5);
    int lane = t & 31;
    const float* xr = x + row * 256;

    float xv[8];
    #pragma unroll
    for (int u = 0; u < 8; ++u) xv[u] = xr[(u << 5) + lane];

    unsigned short* xo = (unsigned short*)g_xh + row * 256 + lane;
    #pragma unroll
    for (int u = 0; u < 8; ++u) {
        __half hv = __float2half_rn(xv[u]);
        xo[u << 5] = *(unsigned short*)&hv;
    }

    float s[8];
    #pragma unroll
    for (int c = 0; c < 8; ++c) {
        float p = 0.f;
        #pragma unroll
        for (int u = 0; u < 8; ++u)
            p = fmaf(xv[u], Wa_s[((u << 5) + lane) * 9 + c], p);
        #pragma unroll
        for (int o = 16; o; o >>= 1) p += __shfl_xor_sync(0xffffffffu, p, o);
        s[c] = p;
    }
    if (lane == 0) {
        int b = row >> 10;
        #pragma unroll
        for (int h = 0; h < 4; ++h) {
            g_ssrc[row * 4 + h] = s[h];
            g_sdst[row * 4 + h] = s[4 + h];
            atomicMaxFloat(&g_mx[b * 4 + h], s[4 + h]);
        }
    }
}

// ============================================================
// [2] h = x @ W via HMMA -> g_hh (unchanged)
// ============================================================
__global__ __launch_bounds__(256, 1)
void hgemm_kernel(float* __restrict__ dummy)
{
    extern __shared__ __align__(16) char sg[];
    const uint32_t sbA = smem_u32(sg);
    const uint32_t sbB = sbA + 2 * ABUF;

    const int t = threadIdx.x;
    const int lane = t & 31, w = t >> 5;
    const int nBase = blockIdx.x << 7;
    const int mBase = blockIdx.y << 7;

    const char* aSrc = (const char*)g_xh + (size_t)mBase * 512;
    const char* bSrc = (const char*)g_Wh + (size_t)nBase * 2;

    #pragma unroll
    for (int kc = 0; kc < 2; ++kc) {
        #pragma unroll
        for (int l = 0; l < 4; ++l) {
            int idx = t + (l << 8);
            CP_ASYNC16(sbA + kc * ABUF + (idx >> 3) * AROWG + ((idx & 7) << 4),
                       aSrc + (size_t)(idx >> 3) * 512 + kc * 128 + ((idx & 7) << 4));
        }
        #pragma unroll
        for (int l = 0; l < 4; ++l) {
            int idx = t + (l << 8);
            CP_ASYNC16(sbB + kc * BBUF + (idx >> 4) * BROWG + ((idx & 15) << 4),
                       bSrc + (size_t)(kc * 64 + (idx >> 4)) * 512 + ((idx & 15) << 4));
        }
        CP_COMMIT();
    }

    const int mw = w & 3, nw = w >> 2;
    const uint32_t aBase = sbA + ((mw << 5) + (lane & 15)) * AROWG + ((lane >> 4) << 4);
    const uint32_t bBase = sbB + (lane & 15) * BROWG + ((lane >> 4) << 4) + (nw << 7);

    float acc[2][8][4];
    #pragma unroll
    for (int f = 0; f < 2; ++f)
        #pragma unroll
        for (int n = 0; n < 8; ++n)
            #pragma unroll
            for (int c = 0; c < 4; ++c) acc[f][n][c] = 0.f;

    for (int kc = 0; kc < 4; ++kc) {
        if (kc + 2 < 4) { CP_WAIT1(); } else { CP_WAIT0(); }
        __syncthreads();
        const uint32_t aB = aBase + (kc & 1) * ABUF;
        const uint32_t bB = bBase + (kc & 1) * BBUF;
        #pragma unroll
        for (int ks = 0; ks < 4; ++ks) {
            uint32_t Af[2][4];
            ldsm_x4(Af[0], aB + (ks << 5));
            ldsm_x4(Af[1], aB + 16 * AROWG + (ks << 5));
            #pragma unroll
            for (int nn = 0; nn < 4; ++nn) {
                uint32_t Bf[4];
                ldsm_x4t(Bf, bB + ks * (16 * BROWG) + (nn << 5));
                mma16816(acc[0][2 * nn],     Af[0], Bf[0], Bf[1]);
                mma16816(acc[0][2 * nn + 1], Af[0], Bf[2], Bf[3]);
                mma16816(acc[1][2 * nn],     Af[1], Bf[0], Bf[1]);
                mma16816(acc[1][2 * nn + 1], Af[1], Bf[2], Bf[3]);
            }
        }
        __syncthreads();
        if (kc + 2 < 4) {
            int kn = kc + 2;
            #pragma unroll
            for (int l = 0; l < 4; ++l) {
                int idx = t + (l << 8);
                CP_ASYNC16(sbA + (kc & 1) * ABUF + (idx >> 3) * AROWG + ((idx & 7) << 4),
                           aSrc + (size_t)(idx >> 3) * 512 + kn * 128 + ((idx & 7) << 4));
            }
            #pragma unroll
            for (int l = 0; l < 4; ++l) {
                int idx = t + (l << 8);
                CP_ASYNC16(sbB + (kc & 1) * BBUF + (idx >> 4) * BROWG + ((idx & 15) << 4),
                           bSrc + (size_t)(kn * 64 + (idx >> 4)) * 512 + ((idx & 15) << 4));
            }
            CP_COMMIT();
        }
    }

    #pragma unroll
    for (int f = 0; f < 2; ++f) {
        int row0 = mBase + (mw << 5) + (f << 4) + (lane >> 2);
        #pragma unroll
        for (int n = 0; n < 8; ++n) {
            int col = nBase + (nw << 6) + (n << 3) + ((lane & 3) << 1);
            __half2 lo = __floats2half2_rn(acc[f][n][0], acc[f][n][1]);
            __half2 hi = __floats2half2_rn(acc[f][n][2], acc[f][n][3]);
            *(uint32_t*)((unsigned short*)g_hh + row0 * 256 + col)       = *(uint32_t*)&lo;
            *(uint32_t*)((unsigned short*)g_hh + (row0 + 8) * 256 + col) = *(uint32_t*)&hi;
        }
    }
    (void)dummy;
}

// ============================================================
// [3] HMMA attention aggregation, deep-pipelined.
//     CTA = (b, 64-row i-tile), 256 thr / 8 warps, grid 256, 1 CTA/SM.
//     j-tile 64; S double-buffered (weights(jt+1) overlap MMA(jt)),
//     H triple-buffered cp.async. ONE barrier per window.
// ============================================================
__global__ __launch_bounds__(256, 1)
void attn_mma_kernel(const int* __restrict__ adj, float* __restrict__ out)
{
    extern __shared__ __align__(16) char sb[];
    const uint32_t sbS = smem_u32(sb);
    const uint32_t sbH = sbS + 2 * S_BYTES;

    __shared__ float4 As_s[NN], Bs_s[NN];          // 32 KB: exp(sdst), exp(.2 sdst)
    __shared__ float4 den_part[4][64];             // 4 KB

    const int t = threadIdx.x;
    const int lane = t & 31, w = t >> 5;
    const int b  = blockIdx.x >> 4;
    const int i0 = (blockIdx.x & 15) << 6;

    // ---- prologue: prefetch H(0)->buf0, H(1)->buf1
    const char* hsrc = (const char*)g_hh + ((size_t)(b << 10) << 9);
    #pragma unroll
    for (int kc = 0; kc < 2; ++kc) {
        #pragma unroll
        for (int l = 0; l < 8; ++l) {
            int idx = t + (l << 8);                // 0..2047 (64 rows x 32 chunks)
            CP_ASYNC16(sbH + kc * HTILE + (idx >> 5) * HROW + ((idx & 31) << 4),
                       hsrc + (size_t)kc * (64 * 512) + ((size_t)idx << 4));
        }
        CP_COMMIT();
    }

    // ---- fused prep: eA/eB for all 1024 rows of this batch
    for (int k = t; k < NN; k += 256) {
        float4 sd = ((const float4*)g_sdst)[(b << 10) + k];
        As_s[k] = make_float4(__expf(sd.x), __expf(sd.y), __expf(sd.z), __expf(sd.w));
        Bs_s[k] = make_float4(__expf(NEG_SLOPE * sd.x), __expf(NEG_SLOPE * sd.y),
                              __expf(NEG_SLOPE * sd.z), __expf(NEG_SLOPE * sd.w));
    }

    // ---- per-row factors P/Q/R
    const int iw = t & 63;
    const int jc = t >> 6;       // 16-j chunk
    float4 P4, Q4, R4;
    {
        float4 ss = ((const float4*)g_ssrc)[(b << 10) + i0 + iw];
        float4 mx = ((const float4*)g_mx)[b];
        float4 M;
        M.x = ss.x + mx.x; M.x = fmaxf(M.x, NEG_SLOPE * M.x);
        M.y = ss.y + mx.y; M.y = fmaxf(M.y, NEG_SLOPE * M.y);
        M.z = ss.z + mx.z; M.z = fmaxf(M.z, NEG_SLOPE * M.z);
        M.w = ss.w + mx.w; M.w = fmaxf(M.w, NEG_SLOPE * M.w);
        P4 = make_float4(__expf(ss.x - M.x), __expf(ss.y - M.y),
                         __expf(ss.z - M.z), __expf(ss.w - M.w));
        Q4 = make_float4(__expf(NEG_SLOPE * ss.x - M.x), __expf(NEG_SLOPE * ss.y - M.y),
                         __expf(NEG_SLOPE * ss.z - M.z), __expf(NEG_SLOPE * ss.w - M.w));
        R4 = make_float4(__expf(-ss.x), __expf(-ss.y), __expf(-ss.z), __expf(-ss.w));
    }
    const int4* arow = (const int4*)(adj + (((size_t)(b << 10) + i0 + iw) << 10) + (jc << 4));
    float d0 = 0.f, d1 = 0.f, d2 = 0.f, d3 = 0.f;

    // mma identity: head hg = w>>1, n32 chunk nc = w&1
    const int hg = w >> 1, nc = w & 1;
    const uint32_t aBase = sbS + hg * SHEAD + (lane & 15) * SROW + ((lane >> 4) << 4);
    const uint32_t bBase = sbH + (lane & 15) * HROW + ((lane >> 4) << 4)
                         + (hg << 7) + (nc << 6);

    float acc[4][4][4];
    #pragma unroll
    for (int mi = 0; mi < 4; ++mi)
        #pragma unroll
        for (int f = 0; f < 4; ++f)
            #pragma unroll
            for (int c = 0; c < 4; ++c) acc[mi][f][c] = 0.f;

    __syncthreads();                               // As_s/Bs_s ready

    // ---- weights S(0) -> S buffer 0
    {
        const int4 mv[4] = { arow[0], arow[1], arow[2], arow[3] };
        const int* mvi = (const int*)mv;
        #pragma unroll
        for (int gHalf = 0; gHalf < 2; ++gHalf) {
            uint32_t pk[4][4];
            float wl[4];
            #pragma unroll
            for (int pp = 0; pp < 8; ++pp) {
                int jl = (jc << 4) + (gHalf << 3) + pp;
                float4 A4 = As_s[jl];
                float4 B4 = Bs_s[jl];
                float msk = (mvi[(gHalf << 3) + pp] > 0) ? 1.f : 0.f;
                float w0 = msk * ((A4.x > R4.x) ? P4.x * A4.x : Q4.x * B4.x);
                float w1 = msk * ((A4.y > R4.y) ? P4.y * A4.y : Q4.y * B4.y);
                float w2 = msk * ((A4.z > R4.z) ? P4.z * A4.z : Q4.z * B4.z);
                float w3 = msk * ((A4.w > R4.w) ? P4.w * A4.w : Q4.w * B4.w);
                d0 += w0; d1 += w1; d2 += w2; d3 += w3;
                if (pp & 1) {
                    __half2 p0 = __floats2half2_rn(wl[0], w0);
                    __half2 p1 = __floats2half2_rn(wl[1], w1);
                    __half2 p2 = __floats2half2_rn(wl[2], w2);
                    __half2 p3 = __floats2half2_rn(wl[3], w3);
                    pk[0][pp >> 1] = *(uint32_t*)&p0;
                    pk[1][pp >> 1] = *(uint32_t*)&p1;
                    pk[2][pp >> 1] = *(uint32_t*)&p2;
                    pk[3][pp >> 1] = *(uint32_t*)&p3;
                } else { wl[0] = w0; wl[1] = w1; wl[2] = w2; wl[3] = w3; }
            }
            const uint32_t base = sbS + iw * SROW + (jc << 5) + (gHalf << 4);
            #pragma unroll
            for (int hh = 0; hh < 4; ++hh)
                asm volatile("st.shared.v4.b32 [%0], {%1,%2,%3,%4};"
                    :: "r"(base + hh * SHEAD),
                       "r"(pk[hh][0]), "r"(pk[hh][1]), "r"(pk[hh][2]), "r"(pk[hh][3]) : "memory");
        }
    }
    CP_WAIT1();                                    // H(0) arrived
    __syncthreads();

    for (int jt = 0; jt < 16; ++jt) {
        // ---- prefetch H(jt+2) into buf (jt+2)%3 (free: MMA(jt-1) done by all)
        if (jt + 2 < 16) {
            const char* src = hsrc + (size_t)(jt + 2) * (64 * 512);
            const uint32_t dst = sbH + ((jt + 2) % 3) * HTILE;
            #pragma unroll
            for (int l = 0; l < 8; ++l) {
                int idx = t + (l << 8);
                CP_ASYNC16(dst + (idx >> 5) * HROW + ((idx & 31) << 4),
                           src + ((size_t)idx << 4));
            }
            CP_COMMIT();
        }

        // ---- MMA(jt): S buf jt&1, H buf jt%3
        {
            const uint32_t aB = aBase + (jt & 1) * S_BYTES;
            const uint32_t bB = bBase + (jt % 3) * HTILE;
            #pragma unroll
            for (int ks = 0; ks < 4; ++ks) {
                uint32_t Af[4][4];
                #pragma unroll
                for (int mi = 0; mi < 4; ++mi)
                    ldsm_x4(Af[mi], aB + mi * (16 * SROW) + (ks << 5));
                #pragma unroll
                for (int nn = 0; nn < 2; ++nn) {
                    uint32_t Bf[4];
                    ldsm_x4t(Bf, bB + ks * (16 * HROW) + (nn << 5));
                    #pragma unroll
                    for (int mi = 0; mi < 4; ++mi) {
                        mma16816(acc[mi][2 * nn],     Af[mi], Bf[0], Bf[1]);
                        mma16816(acc[mi][2 * nn + 1], Af[mi], Bf[2], Bf[3]);
                    }
                }
            }
        }
        if (jt == 15) break;

        // ---- weights S(jt+1) -> S buf (jt+1)&1 (opposite of MMA's buffer)
        {
            const int jn = jt + 1;
            const int4 mv[4] = { arow[(jn << 4) + 0], arow[(jn << 4) + 1],
                                 arow[(jn << 4) + 2], arow[(jn << 4) + 3] };
            const int* mvi = (const int*)mv;
            const int j0 = jn << 6;
            #pragma unroll
            for (int gHalf = 0; gHalf < 2; ++gHalf) {
                uint32_t pk[4][4];
                float wl[4];
                #pragma unroll
                for (int pp = 0; pp < 8; ++pp) {
                    int jl = (jc << 4) + (gHalf << 3) + pp;
                    float4 A4 = As_s[j0 + jl];
                    float4 B4 = Bs_s[j0 + jl];
                    float msk = (mvi[(gHalf << 3) + pp] > 0) ? 1.f : 0.f;
                    float w0 = msk * ((A4.x > R4.x) ? P4.x * A4.x : Q4.x * B4.x);
                    float w1 = msk * ((A4.y > R4.y) ? P4.y * A4.y : Q4.y * B4.y);
                    float w2 = msk * ((A4.z > R4.z) ? P4.z * A4.z : Q4.z * B4.z);
                    float w3 = msk * ((A4.w > R4.w) ? P4.w * A4.w : Q4.w * B4.w);
                    d0 += w0; d1 += w1; d2 += w2; d3 += w3;
                    if (pp & 1) {
                        __half2 p0 = __floats2half2_rn(wl[0], w0);
                        __half2 p1 = __floats2half2_rn(wl[1], w1);
                        __half2 p2 = __floats2half2_rn(wl[2], w2);
                        __half2 p3 = __floats2half2_rn(wl[3], w3);
                        pk[0][pp >> 1] = *(uint32_t*)&p0;
                        pk[1][pp >> 1] = *(uint32_t*)&p1;
                        pk[2][pp >> 1] = *(uint32_t*)&p2;
                        pk[3][pp >> 1] = *(uint32_t*)&p3;
                    } else { wl[0] = w0; wl[1] = w1; wl[2] = w2; wl[3] = w3; }
                }
                const uint32_t base = sbS + ((jn & 1) ? S_BYTES : 0)
                                    + iw * SROW + (jc << 5) + (gHalf << 4);
                #pragma unroll
                for (int hh = 0; hh < 4; ++hh)
                    asm volatile("st.shared.v4.b32 [%0], {%1,%2,%3,%4};"
                        :: "r"(base + hh * SHEAD),
                           "r"(pk[hh][0]), "r"(pk[hh][1]), "r"(pk[hh][2]), "r"(pk[hh][3]) : "memory");
            }
        }

        if (jt + 2 < 16) { CP_WAIT1(); } else { CP_WAIT0(); }   // H(jt+1) arrived
        __syncthreads();                           // ONE barrier per window
    }

    // ---- denominator reduce + normalize + store
    den_part[jc][iw] = make_float4(d0, d1, d2, d3);
    __syncthreads();
    if (t < 64) {
        float4 a0 = den_part[0][t], a1 = den_part[1][t], a2 = den_part[2][t], a3 = den_part[3][t];
        den_part[0][t] = make_float4(a0.x + a1.x + a2.x + a3.x,
                                     a0.y + a1.y + a2.y + a3.y,
                                     a0.z + a1.z + a2.z + a3.z,
                                     a0.w + a1.w + a2.w + a3.w);
    }
    __syncthreads();

    const float* denf = (const float*)&den_part[0][0];
    #pragma unroll
    for (int mi = 0; mi < 4; ++mi) {
        const int row_lo = (mi << 4) + (lane >> 2);
        float dv0 = 1.f / denf[row_lo * 4 + hg];
        float dv1 = 1.f / denf[(row_lo + 8) * 4 + hg];
        #pragma unroll
        for (int f = 0; f < 4; ++f) {
            int col = (hg << 6) + (nc << 5) + (f << 3) + ((lane & 3) << 1);
            *(float2*)(out + ((b << 10) + i0 + row_lo) * 256 + col) =
                make_float2(acc[mi][f][0] * dv0, acc[mi][f][1] * dv0);
            *(float2*)(out + ((b << 10) + i0 + row_lo + 8) * 256 + col) =
                make_float2(acc[mi][f][2] * dv1, acc[mi][f][3] * dv1);
        }
    }
}

// ============================================================
extern "C" void kernel_launch(void* const* d_in, const int* in_sizes, int n_in,
                              void* d_out, int out_size)
{
    cudaFuncSetAttribute(attn_mma_kernel, cudaFuncAttributeMaxDynamicSharedMemorySize, DYN_BYTES);
    cudaFuncSetAttribute(hgemm_kernel, cudaFuncAttributeMaxDynamicSharedMemorySize, GEMM_DYN);

    const float* x = nullptr; const int* adj = nullptr;
    const float* W = nullptr; const float* a = nullptr;
    for (int i = 0; i < n_in; ++i) {
        int s = in_sizes[i];
        if      (s == BB * NN * INF) x   = (const float*)d_in[i];
        else if (s == BB * NN * NN)  adj = (const int*)d_in[i];
        else if (s == INF * HH * 64) W   = (const float*)d_in[i];
        else if (s == 2 * 64 * HH)   a   = (const float*)d_in[i];
    }

    prep0_kernel<<<72, 256>>>(W, a);                                   // idx 0
    score_kernel<<<2048, 256>>>(x);                                    // idx 1
    hgemm_kernel<<<dim3(2, 128), 256, GEMM_DYN>>>(nullptr);            // idx 2
    attn_mma_kernel<<<BB * (NN / 64), 256, DYN_BYTES>>>(adj, (float*)d_out);  // idx 3 -> profiled
}

// round 15
// speedup vs baseline: 1.1991x; 1.0970x over previous
#include <cuda_runtime.h>
#include <cuda_fp16.h>
#include <cstdint>

#define BB   16
#define NN   1024
#define INF  256
#define HH   4
#define NEG_SLOPE 0.2f

// attn smem: i-tile 64, j-tile 64; S double-buffered, H triple-buffered
#define SROW   144                // 64 j * 2B + 16B pad
#define SHEAD  (64 * SROW)        // 9216
#define S_BYTES (4 * SHEAD)       // 36864 per S buffer
#define HROW   528                // 256 c * 2B + 16B pad
#define HTILE  (64 * HROW)        // 33792 per H buffer
#define DYN_BYTES (2 * S_BYTES + 3 * HTILE)   // 175104

// hgemm smem: 128m x 128n block, k-chunk 64, double buffered
#define AROWG  144
#define ABUF   (128 * AROWG)      // 18432
#define BROWG  272
#define BBUF   (64 * BROWG)       // 17408
#define GEMM_DYN (2 * (ABUF + BBUF))   // 71680

// ---- scratch ----
__device__ __half g_xh[BB * NN * 256];
__device__ __half g_Wh[256 * 256];
__device__ float  g_Wa[256 * 8];
__device__ __half g_hh[BB * NN * 256];
__device__ float  g_ssrc[BB * NN * HH];
__device__ float  g_sdst[BB * NN * HH];
#define NEG16 -1e30f,-1e30f,-1e30f,-1e30f,-1e30f,-1e30f,-1e30f,-1e30f,\
              -1e30f,-1e30f,-1e30f,-1e30f,-1e30f,-1e30f,-1e30f,-1e30f
__device__ float  g_mx[BB * HH] = { NEG16, NEG16, NEG16, NEG16 };

// ---- helpers ----
__device__ __forceinline__ uint32_t smem_u32(const void* p) {
    uint32_t a;
    asm("{ .reg .u64 t; cvta.to.shared.u64 t, %1; cvt.u32.u64 %0, t; }" : "=r"(a) : "l"(p));
    return a;
}
__device__ __forceinline__ void ldsm_x4(uint32_t* d, uint32_t addr) {
    asm volatile("ldmatrix.sync.aligned.m8n8.x4.shared.b16 {%0,%1,%2,%3}, [%4];"
        : "=r"(d[0]), "=r"(d[1]), "=r"(d[2]), "=r"(d[3]) : "r"(addr));
}
__device__ __forceinline__ void ldsm_x4t(uint32_t* d, uint32_t addr) {
    asm volatile("ldmatrix.sync.aligned.m8n8.x4.trans.shared.b16 {%0,%1,%2,%3}, [%4];"
        : "=r"(d[0]), "=r"(d[1]), "=r"(d[2]), "=r"(d[3]) : "r"(addr));
}
__device__ __forceinline__ void mma16816(float* c, const uint32_t* a, uint32_t b0, uint32_t b1) {
    asm volatile("mma.sync.aligned.m16n8k16.row.col.f32.f16.f16.f32 "
        "{%0,%1,%2,%3}, {%4,%5,%6,%7}, {%8,%9}, {%0,%1,%2,%3};"
        : "+f"(c[0]), "+f"(c[1]), "+f"(c[2]), "+f"(c[3])
        : "r"(a[0]), "r"(a[1]), "r"(a[2]), "r"(a[3]), "r"(b0), "r"(b1));
}
#define CP_ASYNC16(smem, gptr) \
    asm volatile("cp.async.cg.shared.global [%0], [%1], 16;" :: "r"(smem), "l"(gptr) : "memory")
#define CP_COMMIT() asm volatile("cp.async.commit_group;" ::: "memory")
#define CP_WAIT1()  asm volatile("cp.async.wait_group 1;" ::: "memory")
#define CP_WAIT0()  asm volatile("cp.async.wait_group 0;" ::: "memory")

__device__ __forceinline__ void atomicMaxFloat(float* a, float v) {
    if (v >= 0.f) atomicMax((int*)a, __float_as_int(v));
    else          atomicMin((unsigned int*)a, __float_as_uint(v));
}

// ============================================================
// [0] fused: W -> fp16 (blocks 0..63) + Wa = W @ [a_src|a_dst] (blocks 64..71)
// ============================================================
__global__ __launch_bounds__(256) void prep0_kernel(const float* __restrict__ W,
                                                    const float* __restrict__ av)
{
    if (blockIdx.x < 64) {
        int i = (blockIdx.x * 256 + threadIdx.x) << 2;
        float4 v = *(const float4*)&W[i];
        __half2 h0 = __floats2half2_rn(v.x, v.y);
        __half2 h1 = __floats2half2_rn(v.z, v.w);
        *(uint2*)((unsigned short*)g_Wh + i) = make_uint2(*(uint32_t*)&h0, *(uint32_t*)&h1);
    } else {
        int c = blockIdx.x - 64;
        int h = c & 3;
        int dbase = (c >= 4) ? 64 : 0;
        int k = threadIdx.x;
        float p = 0.f;
        #pragma unroll 16
        for (int d = 0; d < 64; ++d)
            p = fmaf(W[k * 256 + h * 64 + d], av[(dbase + d) * 4 + h], p);
        g_Wa[k * 8 + c] = p;
    }
}

// ============================================================
// [1] scores s = x @ Wa (fp32, exact) + global max + x -> fp16
// ============================================================
__global__ __launch_bounds__(256) void score_kernel(const float* __restrict__ x)
{
    __shared__ float Wa_s[256 * 9];
    int t = threadIdx.x;
    for (int i = t; i < 2048; i += 256)
        Wa_s[(i >> 3) * 9 + (i & 7)] = g_Wa[i];
    __syncthreads();

    int row  = blockIdx.x * 8 + (t >> 5);
    int lane = t & 31;
    const float* xr = x + row * 256;

    float xv[8];
    #pragma unroll
    for (int u = 0; u < 8; ++u) xv[u] = xr[(u << 5) + lane];

    unsigned short* xo = (unsigned short*)g_xh + row * 256 + lane;
    #pragma unroll
    for (int u = 0; u < 8; ++u) {
        __half hv = __float2half_rn(xv[u]);
        xo[u << 5] = *(unsigned short*)&hv;
    }

    float s[8];
    #pragma unroll
    for (int c = 0; c < 8; ++c) {
        float p = 0.f;
        #pragma unroll
        for (int u = 0; u < 8; ++u)
            p = fmaf(xv[u], Wa_s[((u << 5) + lane) * 9 + c], p);
        #pragma unroll
        for (int o = 16; o; o >>= 1) p += __shfl_xor_sync(0xffffffffu, p, o);
        s[c] = p;
    }
    if (lane == 0) {
        int b = row >> 10;
        #pragma unroll
        for (int h = 0; h < 4; ++h) {
            g_ssrc[row * 4 + h] = s[h];
            g_sdst[row * 4 + h] = s[4 + h];
            atomicMaxFloat(&g_mx[b * 4 + h], s[4 + h]);
        }
    }
}

// ============================================================
// [2] h = x @ W via HMMA -> g_hh (unchanged)
// ============================================================
__global__ __launch_bounds__(256, 1)
void hgemm_kernel(float* __restrict__ dummy)
{
    extern __shared__ __align__(16) char sg[];
    const uint32_t sbA = smem_u32(sg);
    const uint32_t sbB = sbA + 2 * ABUF;

    const int t = threadIdx.x;
    const int lane = t & 31, w = t >> 5;
    const int nBase = blockIdx.x << 7;
    const int mBase = blockIdx.y << 7;

    const char* aSrc = (const char*)g_xh + (size_t)mBase * 512;
    const char* bSrc = (const char*)g_Wh + (size_t)nBase * 2;

    #pragma unroll
    for (int kc = 0; kc < 2; ++kc) {
        #pragma unroll
        for (int l = 0; l < 4; ++l) {
            int idx = t + (l << 8);
            CP_ASYNC16(sbA + kc * ABUF + (idx >> 3) * AROWG + ((idx & 7) << 4),
                       aSrc + (size_t)(idx >> 3) * 512 + kc * 128 + ((idx & 7) << 4));
        }
        #pragma unroll
        for (int l = 0; l < 4; ++l) {
            int idx = t + (l << 8);
            CP_ASYNC16(sbB + kc * BBUF + (idx >> 4) * BROWG + ((idx & 15) << 4),
                       bSrc + (size_t)(kc * 64 + (idx >> 4)) * 512 + ((idx & 15) << 4));
        }
        CP_COMMIT();
    }

    const int mw = w & 3, nw = w >> 2;
    const uint32_t aBase = sbA + ((mw << 5) + (lane & 15)) * AROWG + ((lane >> 4) << 4);
    const uint32_t bBase = sbB + (lane & 15) * BROWG + ((lane >> 4) << 4) + (nw << 7);

    float acc[2][8][4];
    #pragma unroll
    for (int f = 0; f < 2; ++f)
        #pragma unroll
        for (int n = 0; n < 8; ++n)
            #pragma unroll
            for (int c = 0; c < 4; ++c) acc[f][n][c] = 0.f;

    for (int kc = 0; kc < 4; ++kc) {
        if (kc + 2 < 4) { CP_WAIT1(); } else { CP_WAIT0(); }
        __syncthreads();
        const uint32_t aB = aBase + (kc & 1) * ABUF;
        const uint32_t bB = bBase + (kc & 1) * BBUF;
        #pragma unroll
        for (int ks = 0; ks < 4; ++ks) {
            uint32_t Af[2][4];
            ldsm_x4(Af[0], aB + (ks << 5));
            ldsm_x4(Af[1], aB + 16 * AROWG + (ks << 5));
            #pragma unroll
            for (int nn = 0; nn < 4; ++nn) {
                uint32_t Bf[4];
                ldsm_x4t(Bf, bB + ks * (16 * BROWG) + (nn << 5));
                mma16816(acc[0][2 * nn],     Af[0], Bf[0], Bf[1]);
                mma16816(acc[0][2 * nn + 1], Af[0], Bf[2], Bf[3]);
                mma16816(acc[1][2 * nn],     Af[1], Bf[0], Bf[1]);
                mma16816(acc[1][2 * nn + 1], Af[1], Bf[2], Bf[3]);
            }
        }
        __syncthreads();
        if (kc + 2 < 4) {
            int kn = kc + 2;
            #pragma unroll
            for (int l = 0; l < 4; ++l) {
                int idx = t + (l << 8);
                CP_ASYNC16(sbA + (kc & 1) * ABUF + (idx >> 3) * AROWG + ((idx & 7) << 4),
                           aSrc + (size_t)(idx >> 3) * 512 + kn * 128 + ((idx & 7) << 4));
            }
            #pragma unroll
            for (int l = 0; l < 4; ++l) {
                int idx = t + (l << 8);
                CP_ASYNC16(sbB + (kc & 1) * BBUF + (idx >> 4) * BROWG + ((idx & 15) << 4),
                           bSrc + (size_t)(kn * 64 + (idx >> 4)) * 512 + ((idx & 15) << 4));
            }
            CP_COMMIT();
        }
    }

    #pragma unroll
    for (int f = 0; f < 2; ++f) {
        int row0 = mBase + (mw << 5) + (f << 4) + (lane >> 2);
        #pragma unroll
        for (int n = 0; n < 8; ++n) {
            int col = nBase + (nw << 6) + (n << 3) + ((lane & 3) << 1);
            __half2 lo = __floats2half2_rn(acc[f][n][0], acc[f][n][1]);
            __half2 hi = __floats2half2_rn(acc[f][n][2], acc[f][n][3]);
            *(uint32_t*)((unsigned short*)g_hh + row0 * 256 + col)       = *(uint32_t*)&lo;
            *(uint32_t*)((unsigned short*)g_hh + (row0 + 8) * 256 + col) = *(uint32_t*)&hi;
        }
    }
    (void)dummy;
}

// ============================================================
// [3] HMMA attention aggregation, 512 threads / 16 warps.
//     CTA = (b, 64-row i-tile), grid 256. j-tile 64.
//     S double-buffered (weights(jt+1) overlap MMA(jt)), H triple-buffered.
//     MMA warp = (head hg = w>>2, m32-half mh = (w>>1)&1, n32 nc = w&1):
//     per window 4ks x (2 A-ldsm + 2 B-ldsm + 8 mma) = 32 mma/warp.
//     Weight thread = (row iw = t&63, 8-j chunk jc = t>>6).
// ============================================================
__global__ __launch_bounds__(512, 1)
void attn_mma_kernel(const int* __restrict__ adj, float* __restrict__ out)
{
    extern __shared__ __align__(16) char sb[];
    const uint32_t sbS = smem_u32(sb);
    const uint32_t sbH = sbS + 2 * S_BYTES;

    __shared__ float4 As_s[NN], Bs_s[NN];          // 32 KB
    __shared__ float4 den_part[8][64];             // 8 KB

    const int t = threadIdx.x;
    const int lane = t & 31, w = t >> 5;
    const int b  = blockIdx.x >> 4;
    const int i0 = (blockIdx.x & 15) << 6;

    // ---- prologue: prefetch H(0)->buf0, H(1)->buf1 (4 uint4/thread each)
    const char* hsrc = (const char*)g_hh + ((size_t)(b << 10) << 9);
    #pragma unroll
    for (int kc = 0; kc < 2; ++kc) {
        #pragma unroll
        for (int l = 0; l < 4; ++l) {
            int idx = t + (l << 9);                // 0..2047
            CP_ASYNC16(sbH + kc * HTILE + (idx >> 5) * HROW + ((idx & 31) << 4),
                       hsrc + (size_t)kc * (64 * 512) + ((size_t)idx << 4));
        }
        CP_COMMIT();
    }

    // ---- fused prep: eA/eB for all 1024 rows of this batch
    for (int k = t; k < NN; k += 512) {
        float4 sd = ((const float4*)g_sdst)[(b << 10) + k];
        As_s[k] = make_float4(__expf(sd.x), __expf(sd.y), __expf(sd.z), __expf(sd.w));
        Bs_s[k] = make_float4(__expf(NEG_SLOPE * sd.x), __expf(NEG_SLOPE * sd.y),
                              __expf(NEG_SLOPE * sd.z), __expf(NEG_SLOPE * sd.w));
    }

    // ---- per-row factors P/Q/R (weight identity: row iw, 8-j chunk jc)
    const int iw = t & 63;
    const int jc = t >> 6;       // 0..7
    float4 P4, Q4, R4;
    {
        float4 ss = ((const float4*)g_ssrc)[(b << 10) + i0 + iw];
        float4 mx = ((const float4*)g_mx)[b];
        float4 M;
        M.x = ss.x + mx.x; M.x = fmaxf(M.x, NEG_SLOPE * M.x);
        M.y = ss.y + mx.y; M.y = fmaxf(M.y, NEG_SLOPE * M.y);
        M.z = ss.z + mx.z; M.z = fmaxf(M.z, NEG_SLOPE * M.z);
        M.w = ss.w + mx.w; M.w = fmaxf(M.w, NEG_SLOPE * M.w);
        P4 = make_float4(__expf(ss.x - M.x), __expf(ss.y - M.y),
                         __expf(ss.z - M.z), __expf(ss.w - M.w));
        Q4 = make_float4(__expf(NEG_SLOPE * ss.x - M.x), __expf(NEG_SLOPE * ss.y - M.y),
                         __expf(NEG_SLOPE * ss.z - M.z), __expf(NEG_SLOPE * ss.w - M.w));
        R4 = make_float4(__expf(-ss.x), __expf(-ss.y), __expf(-ss.z), __expf(-ss.w));
    }
    const int4* arow = (const int4*)(adj + (((size_t)(b << 10) + i0 + iw) << 10));
    float d0 = 0.f, d1 = 0.f, d2 = 0.f, d3 = 0.f;

    // ---- mma identity: head hg, m32-half mh, n32 chunk nc
    const int hg = w >> 2, mh = (w >> 1) & 1, nc = w & 1;
    const uint32_t aBase = sbS + hg * SHEAD + ((mh << 5) + (lane & 15)) * SROW
                         + ((lane >> 4) << 4);
    const uint32_t bBase = sbH + (lane & 15) * HROW + ((lane >> 4) << 4)
                         + (hg << 7) + (nc << 6);

    float acc[2][4][4];
    #pragma unroll
    for (int mi = 0; mi < 2; ++mi)
        #pragma unroll
        for (int f = 0; f < 4; ++f)
            #pragma unroll
            for (int c = 0; c < 4; ++c) acc[mi][f][c] = 0.f;

    __syncthreads();                               // As_s/Bs_s ready

    // ---- weights S(0) -> S buffer 0 (8 j's per thread)
    {
        const int4 m0 = arow[jc << 1];
        const int4 m1 = arow[(jc << 1) + 1];
        const int mvi[8] = { m0.x, m0.y, m0.z, m0.w, m1.x, m1.y, m1.z, m1.w };
        uint32_t pk[4][4];
        float wl[4];
        #pragma unroll
        for (int pp = 0; pp < 8; ++pp) {
            int jl = (jc << 3) + pp;
            float4 A4 = As_s[jl];
            float4 B4 = Bs_s[jl];
            float msk = (mvi[pp] > 0) ? 1.f : 0.f;
            float w0 = msk * ((A4.x > R4.x) ? P4.x * A4.x : Q4.x * B4.x);
            float w1 = msk * ((A4.y > R4.y) ? P4.y * A4.y : Q4.y * B4.y);
            float w2 = msk * ((A4.z > R4.z) ? P4.z * A4.z : Q4.z * B4.z);
            float w3 = msk * ((A4.w > R4.w) ? P4.w * A4.w : Q4.w * B4.w);
            d0 += w0; d1 += w1; d2 += w2; d3 += w3;
            if (pp & 1) {
                __half2 p0 = __floats2half2_rn(wl[0], w0);
                __half2 p1 = __floats2half2_rn(wl[1], w1);
                __half2 p2 = __floats2half2_rn(wl[2], w2);
                __half2 p3 = __floats2half2_rn(wl[3], w3);
                pk[0][pp >> 1] = *(uint32_t*)&p0;
                pk[1][pp >> 1] = *(uint32_t*)&p1;
                pk[2][pp >> 1] = *(uint32_t*)&p2;
                pk[3][pp >> 1] = *(uint32_t*)&p3;
            } else { wl[0] = w0; wl[1] = w1; wl[2] = w2; wl[3] = w3; }
        }
        const uint32_t base = sbS + iw * SROW + (jc << 4);
        #pragma unroll
        for (int hh = 0; hh < 4; ++hh)
            asm volatile("st.shared.v4.b32 [%0], {%1,%2,%3,%4};"
                :: "r"(base + hh * SHEAD),
                   "r"(pk[hh][0]), "r"(pk[hh][1]), "r"(pk[hh][2]), "r"(pk[hh][3]) : "memory");
    }
    CP_WAIT1();                                    // H(0) arrived
    __syncthreads();

    for (int jt = 0; jt < 16; ++jt) {
        // ---- prefetch H(jt+2) into buf (jt+2)%3
        if (jt + 2 < 16) {
            const char* src = hsrc + (size_t)(jt + 2) * (64 * 512);
            const uint32_t dst = sbH + ((jt + 2) % 3) * HTILE;
            #pragma unroll
            for (int l = 0; l < 4; ++l) {
                int idx = t + (l << 9);
                CP_ASYNC16(dst + (idx >> 5) * HROW + ((idx & 31) << 4),
                           src + ((size_t)idx << 4));
            }
            CP_COMMIT();
        }

        // ---- MMA(jt): S buf jt&1, H buf jt%3
        {
            const uint32_t aB = aBase + (jt & 1) * S_BYTES;
            const uint32_t bB = bBase + (jt % 3) * HTILE;
            #pragma unroll
            for (int ks = 0; ks < 4; ++ks) {
                uint32_t Af[2][4];
                ldsm_x4(Af[0], aB + (ks << 5));
                ldsm_x4(Af[1], aB + 16 * SROW + (ks << 5));
                #pragma unroll
                for (int nn = 0; nn < 2; ++nn) {
                    uint32_t Bf[4];
                    ldsm_x4t(Bf, bB + ks * (16 * HROW) + (nn << 5));
                    mma16816(acc[0][2 * nn],     Af[0], Bf[0], Bf[1]);
                    mma16816(acc[0][2 * nn + 1], Af[0], Bf[2], Bf[3]);
                    mma16816(acc[1][2 * nn],     Af[1], Bf[0], Bf[1]);
                    mma16816(acc[1][2 * nn + 1], Af[1], Bf[2], Bf[3]);
                }
            }
        }
        if (jt == 15) break;

        // ---- weights S(jt+1) -> S buf (jt+1)&1
        {
            const int jn = jt + 1;
            const int j0 = jn << 6;
            const int4 m0 = arow[(jn << 4) + (jc << 1)];
            const int4 m1 = arow[(jn << 4) + (jc << 1) + 1];
            const int mvi[8] = { m0.x, m0.y, m0.z, m0.w, m1.x, m1.y, m1.z, m1.w };
            uint32_t pk[4][4];
            float wl[4];
            #pragma unroll
            for (int pp = 0; pp < 8; ++pp) {
                int jl = (jc << 3) + pp;
                float4 A4 = As_s[j0 + jl];
                float4 B4 = Bs_s[j0 + jl];
                float msk = (mvi[pp] > 0) ? 1.f : 0.f;
                float w0 = msk * ((A4.x > R4.x) ? P4.x * A4.x : Q4.x * B4.x);
                float w1 = msk * ((A4.y > R4.y) ? P4.y * A4.y : Q4.y * B4.y);
                float w2 = msk * ((A4.z > R4.z) ? P4.z * A4.z : Q4.z * B4.z);
                float w3 = msk * ((A4.w > R4.w) ? P4.w * A4.w : Q4.w * B4.w);
                d0 += w0; d1 += w1; d2 += w2; d3 += w3;
                if (pp & 1) {
                    __half2 p0 = __floats2half2_rn(wl[0], w0);
                    __half2 p1 = __floats2half2_rn(wl[1], w1);
                    __half2 p2 = __floats2half2_rn(wl[2], w2);
                    __half2 p3 = __floats2half2_rn(wl[3], w3);
                    pk[0][pp >> 1] = *(uint32_t*)&p0;
                    pk[1][pp >> 1] = *(uint32_t*)&p1;
                    pk[2][pp >> 1] = *(uint32_t*)&p2;
                    pk[3][pp >> 1] = *(uint32_t*)&p3;
                } else { wl[0] = w0; wl[1] = w1; wl[2] = w2; wl[3] = w3; }
            }
            const uint32_t base = sbS + ((jn & 1) ? S_BYTES : 0) + iw * SROW + (jc << 4);
            #pragma unroll
            for (int hh = 0; hh < 4; ++hh)
                asm volatile("st.shared.v4.b32 [%0], {%1,%2,%3,%4};"
                    :: "r"(base + hh * SHEAD),
                       "r"(pk[hh][0]), "r"(pk[hh][1]), "r"(pk[hh][2]), "r"(pk[hh][3]) : "memory");
        }

        if (jt + 2 < 16) { CP_WAIT1(); } else { CP_WAIT0(); }   // H(jt+1) arrived
        __syncthreads();                           // one barrier per window
    }

    // ---- denominator reduce + normalize + store
    den_part[jc][iw] = make_float4(d0, d1, d2, d3);
    __syncthreads();
    if (t < 64) {
        float4 s0 = den_part[0][t];
        #pragma unroll
        for (int q = 1; q < 8; ++q) {
            float4 v = den_part[q][t];
            s0.x += v.x; s0.y += v.y; s0.z += v.z; s0.w += v.w;
        }
        den_part[0][t] = s0;
    }
    __syncthreads();

    const float* denf = (const float*)&den_part[0][0];
    #pragma unroll
    for (int mi = 0; mi < 2; ++mi) {
        const int row_lo = (mh << 5) + (mi << 4) + (lane >> 2);
        float dv0 = 1.f / denf[row_lo * 4 + hg];
        float dv1 = 1.f / denf[(row_lo + 8) * 4 + hg];
        #pragma unroll
        for (int f = 0; f < 4; ++f) {
            int col = (hg << 6) + (nc << 5) + (f << 3) + ((lane & 3) << 1);
            *(float2*)(out + ((b << 10) + i0 + row_lo) * 256 + col) =
                make_float2(acc[mi][f][0] * dv0, acc[mi][f][1] * dv0);
            *(float2*)(out + ((b << 10) + i0 + row_lo + 8) * 256 + col) =
                make_float2(acc[mi][f][2] * dv1, acc[mi][f][3] * dv1);
        }
    }
}

// ============================================================
extern "C" void kernel_launch(void* const* d_in, const int* in_sizes, int n_in,
                              void* d_out, int out_size)
{
    cudaFuncSetAttribute(attn_mma_kernel, cudaFuncAttributeMaxDynamicSharedMemorySize, DYN_BYTES);
    cudaFuncSetAttribute(hgemm_kernel, cudaFuncAttributeMaxDynamicSharedMemorySize, GEMM_DYN);

    const float* x = nullptr; const int* adj = nullptr;
    const float* W = nullptr; const float* a = nullptr;
    for (int i = 0; i < n_in; ++i) {
        int s = in_sizes[i];
        if      (s == BB * NN * INF) x   = (const float*)d_in[i];
        else if (s == BB * NN * NN)  adj = (const int*)d_in[i];
        else if (s == INF * HH * 64) W   = (const float*)d_in[i];
        else if (s == 2 * 64 * HH)   a   = (const float*)d_in[i];
    }

    prep0_kernel<<<72, 256>>>(W, a);                                   // idx 0
    score_kernel<<<2048, 256>>>(x);                                    // idx 1
    hgemm_kernel<<<dim3(2, 128), 256, GEMM_DYN>>>(nullptr);            // idx 2
    attn_mma_kernel<<<BB * (NN / 64), 512, DYN_BYTES>>>(adj, (float*)d_out);  // idx 3 -> profiled
}

// round 16
// speedup vs baseline: 1.3475x; 1.1237x over previous
#include <cuda_runtime.h>
#include <cuda_fp16.h>
#include <cstdint>

#define BB   16
#define NN   1024
#define INF  256
#define HH   4
#define NEG_SLOPE 0.2f

// attn smem: i-tile 64, j-tile 64; S double-buffered, H triple-buffered
#define SROW   144
#define SHEAD  (64 * SROW)        // 9216
#define S_BYTES (4 * SHEAD)       // 36864 per S buffer
#define HROW   528
#define HTILE  (64 * HROW)        // 33792 per H buffer
#define DYN_BYTES (2 * S_BYTES + 3 * HTILE)   // 175104

// hgemm smem: 128m x 128n block, k-chunk 64, double buffered
#define AROWG  144
#define ABUF   (128 * AROWG)      // 18432
#define BROWG  272
#define BBUF   (64 * BROWG)       // 17408
#define GEMM_DYN (2 * (ABUF + BBUF))   // 71680

// ---- scratch ----
__device__ __half g_xh[BB * NN * 256];
__device__ __half g_Wh[256 * 256];
__device__ __half g_hh[BB * NN * 256];
__device__ float  g_ssrc[BB * NN * HH];
__device__ float  g_sdst[BB * NN * HH];
#define NEG16 -1e30f,-1e30f,-1e30f,-1e30f,-1e30f,-1e30f,-1e30f,-1e30f,\
              -1e30f,-1e30f,-1e30f,-1e30f,-1e30f,-1e30f,-1e30f,-1e30f
__device__ float  g_mx[BB * HH] = { NEG16, NEG16, NEG16, NEG16 };

// ---- helpers ----
__device__ __forceinline__ uint32_t smem_u32(const void* p) {
    uint32_t a;
    asm("{ .reg .u64 t; cvta.to.shared.u64 t, %1; cvt.u32.u64 %0, t; }" : "=r"(a) : "l"(p));
    return a;
}
__device__ __forceinline__ void ldsm_x4(uint32_t* d, uint32_t addr) {
    asm volatile("ldmatrix.sync.aligned.m8n8.x4.shared.b16 {%0,%1,%2,%3}, [%4];"
        : "=r"(d[0]), "=r"(d[1]), "=r"(d[2]), "=r"(d[3]) : "r"(addr));
}
__device__ __forceinline__ void ldsm_x4t(uint32_t* d, uint32_t addr) {
    asm volatile("ldmatrix.sync.aligned.m8n8.x4.trans.shared.b16 {%0,%1,%2,%3}, [%4];"
        : "=r"(d[0]), "=r"(d[1]), "=r"(d[2]), "=r"(d[3]) : "r"(addr));
}
__device__ __forceinline__ void mma16816(float* c, const uint32_t* a, uint32_t b0, uint32_t b1) {
    asm volatile("mma.sync.aligned.m16n8k16.row.col.f32.f16.f16.f32 "
        "{%0,%1,%2,%3}, {%4,%5,%6,%7}, {%8,%9}, {%0,%1,%2,%3};"
        : "+f"(c[0]), "+f"(c[1]), "+f"(c[2]), "+f"(c[3])
        : "r"(a[0]), "r"(a[1]), "r"(a[2]), "r"(a[3]), "r"(b0), "r"(b1));
}
#define CP_ASYNC16(smem, gptr) \
    asm volatile("cp.async.cg.shared.global [%0], [%1], 16;" :: "r"(smem), "l"(gptr) : "memory")
#define CP_COMMIT() asm volatile("cp.async.commit_group;" ::: "memory")
#define CP_WAIT1()  asm volatile("cp.async.wait_group 1;" ::: "memory")
#define CP_WAIT0()  asm volatile("cp.async.wait_group 0;" ::: "memory")

__device__ __forceinline__ void atomicMaxFloat(float* a, float v) {
    if (v >= 0.f) atomicMax((int*)a, __float_as_int(v));
    else          atomicMin((unsigned int*)a, __float_as_uint(v));
}

// ============================================================
// [0] fused fp32->fp16 convert: x (blocks 0..4095) + W (4096..4159)
// ============================================================
__global__ __launch_bounds__(256) void cvt_kernel(const float* __restrict__ x,
                                                  const float* __restrict__ W)
{
    int id = blockIdx.x * 256 + threadIdx.x;
    int i  = id << 2;
    const float* src;
    unsigned short* dst;
    if (i < BB * NN * 256) { src = x + i; dst = (unsigned short*)g_xh + i; }
    else { i -= BB * NN * 256; src = W + i; dst = (unsigned short*)g_Wh + i; }
    float4 v = *(const float4*)src;
    __half2 h0 = __floats2half2_rn(v.x, v.y);
    __half2 h1 = __floats2half2_rn(v.z, v.w);
    *(uint2*)dst = make_uint2(*(uint32_t*)&h0, *(uint32_t*)&h1);
}

// ============================================================
// [1] h = x @ W via HMMA -> g_hh, with score GEMV (s = h.a) + global
//     max fused into the epilogue (scores from fp32 accumulators).
//     Block (bx, by): rows by*128.., cols bx*128.. (= heads 2bx, 2bx+1).
//     Warp (mw = w&3: m32, nw = w>>2: head 2bx+nw, full 64 cols).
// ============================================================
__global__ __launch_bounds__(256, 1)
void hgemm_kernel(const float* __restrict__ av)
{
    extern __shared__ __align__(16) char sg[];
    const uint32_t sbA = smem_u32(sg);
    const uint32_t sbB = sbA + 2 * ABUF;
    __shared__ float av_s[512];                    // a: [128][4]

    const int t = threadIdx.x;
    const int lane = t & 31, w = t >> 5;
    const int nBase = blockIdx.x << 7;
    const int mBase = blockIdx.y << 7;

    const char* aSrc = (const char*)g_xh + (size_t)mBase * 512;
    const char* bSrc = (const char*)g_Wh + (size_t)nBase * 2;

    #pragma unroll
    for (int kc = 0; kc < 2; ++kc) {
        #pragma unroll
        for (int l = 0; l < 4; ++l) {
            int idx = t + (l << 8);
            CP_ASYNC16(sbA + kc * ABUF + (idx >> 3) * AROWG + ((idx & 7) << 4),
                       aSrc + (size_t)(idx >> 3) * 512 + kc * 128 + ((idx & 7) << 4));
        }
        #pragma unroll
        for (int l = 0; l < 4; ++l) {
            int idx = t + (l << 8);
            CP_ASYNC16(sbB + kc * BBUF + (idx >> 4) * BROWG + ((idx & 15) << 4),
                       bSrc + (size_t)(kc * 64 + (idx >> 4)) * 512 + ((idx & 15) << 4));
        }
        CP_COMMIT();
    }
    av_s[t] = av[t];
    av_s[256 + t] = av[256 + t];

    const int mw = w & 3, nw = w >> 2;
    const uint32_t aBase = sbA + ((mw << 5) + (lane & 15)) * AROWG + ((lane >> 4) << 4);
    const uint32_t bBase = sbB + (lane & 15) * BROWG + ((lane >> 4) << 4) + (nw << 7);

    float acc[2][8][4];
    #pragma unroll
    for (int f = 0; f < 2; ++f)
        #pragma unroll
        for (int n = 0; n < 8; ++n)
            #pragma unroll
            for (int c = 0; c < 4; ++c) acc[f][n][c] = 0.f;

    for (int kc = 0; kc < 4; ++kc) {
        if (kc + 2 < 4) { CP_WAIT1(); } else { CP_WAIT0(); }
        __syncthreads();
        const uint32_t aB = aBase + (kc & 1) * ABUF;
        const uint32_t bB = bBase + (kc & 1) * BBUF;
        #pragma unroll
        for (int ks = 0; ks < 4; ++ks) {
            uint32_t Af[2][4];
            ldsm_x4(Af[0], aB + (ks << 5));
            ldsm_x4(Af[1], aB + 16 * AROWG + (ks << 5));
            #pragma unroll
            for (int nn = 0; nn < 4; ++nn) {
                uint32_t Bf[4];
                ldsm_x4t(Bf, bB + ks * (16 * BROWG) + (nn << 5));
                mma16816(acc[0][2 * nn],     Af[0], Bf[0], Bf[1]);
                mma16816(acc[0][2 * nn + 1], Af[0], Bf[2], Bf[3]);
                mma16816(acc[1][2 * nn],     Af[1], Bf[0], Bf[1]);
                mma16816(acc[1][2 * nn + 1], Af[1], Bf[2], Bf[3]);
            }
        }
        __syncthreads();
        if (kc + 2 < 4) {
            int kn = kc + 2;
            #pragma unroll
            for (int l = 0; l < 4; ++l) {
                int idx = t + (l << 8);
                CP_ASYNC16(sbA + (kc & 1) * ABUF + (idx >> 3) * AROWG + ((idx & 7) << 4),
                           aSrc + (size_t)(idx >> 3) * 512 + kn * 128 + ((idx & 7) << 4));
            }
            #pragma unroll
            for (int l = 0; l < 4; ++l) {
                int idx = t + (l << 8);
                CP_ASYNC16(sbB + (kc & 1) * BBUF + (idx >> 4) * BROWG + ((idx & 15) << 4),
                           bSrc + (size_t)(kn * 64 + (idx >> 4)) * 512 + ((idx & 15) << 4));
            }
            CP_COMMIT();
        }
    }

    // ---- epilogue 1: h -> fp16 g_hh
    #pragma unroll
    for (int f = 0; f < 2; ++f) {
        int row0 = mBase + (mw << 5) + (f << 4) + (lane >> 2);
        #pragma unroll
        for (int n = 0; n < 8; ++n) {
            int col = nBase + (nw << 6) + (n << 3) + ((lane & 3) << 1);
            __half2 lo = __floats2half2_rn(acc[f][n][0], acc[f][n][1]);
            __half2 hi = __floats2half2_rn(acc[f][n][2], acc[f][n][3]);
            *(uint32_t*)((unsigned short*)g_hh + row0 * 256 + col)       = *(uint32_t*)&lo;
            *(uint32_t*)((unsigned short*)g_hh + (row0 + 8) * 256 + col) = *(uint32_t*)&hi;
        }
    }

    // ---- epilogue 2: scores from fp32 accumulators.
    // This warp's head covers d = (n<<3)+((lane&3)<<1)+{0,1}.
    const int head = (nBase >> 6) + nw;
    float sc[2][2][2];   // [f][rhalf][src/dst]
    #pragma unroll
    for (int f = 0; f < 2; ++f)
        #pragma unroll
        for (int rh = 0; rh < 2; ++rh) { sc[f][rh][0] = 0.f; sc[f][rh][1] = 0.f; }
    #pragma unroll
    for (int n = 0; n < 8; ++n) {
        int d0 = (n << 3) + ((lane & 3) << 1);
        float as0 = av_s[d0 * 4 + head],        as1 = av_s[(d0 + 1) * 4 + head];
        float ad0 = av_s[(64 + d0) * 4 + head], ad1 = av_s[(64 + d0 + 1) * 4 + head];
        #pragma unroll
        for (int f = 0; f < 2; ++f) {
            sc[f][0][0] += acc[f][n][0] * as0 + acc[f][n][1] * as1;
            sc[f][0][1] += acc[f][n][0] * ad0 + acc[f][n][1] * ad1;
            sc[f][1][0] += acc[f][n][2] * as0 + acc[f][n][3] * as1;
            sc[f][1][1] += acc[f][n][2] * ad0 + acc[f][n][3] * ad1;
        }
    }
    #pragma unroll
    for (int o = 1; o < 4; o <<= 1)
        #pragma unroll
        for (int f = 0; f < 2; ++f)
            #pragma unroll
            for (int rh = 0; rh < 2; ++rh) {
                sc[f][rh][0] += __shfl_xor_sync(0xffffffffu, sc[f][rh][0], o);
                sc[f][rh][1] += __shfl_xor_sync(0xffffffffu, sc[f][rh][1], o);
            }
    if ((lane & 3) == 0) {
        #pragma unroll
        for (int f = 0; f < 2; ++f)
            #pragma unroll
            for (int rh = 0; rh < 2; ++rh) {
                int row = mBase + (mw << 5) + (f << 4) + (lane >> 2) + (rh << 3);
                g_ssrc[row * 4 + head] = sc[f][rh][0];
                g_sdst[row * 4 + head] = sc[f][rh][1];
                atomicMaxFloat(&g_mx[(row >> 10) * 4 + head], sc[f][rh][1]);
            }
    }
}

// ============================================================
// [2] HMMA attention aggregation (r15 winner, unchanged).
// ============================================================
__global__ __launch_bounds__(512, 1)
void attn_mma_kernel(const int* __restrict__ adj, float* __restrict__ out)
{
    extern __shared__ __align__(16) char sb[];
    const uint32_t sbS = smem_u32(sb);
    const uint32_t sbH = sbS + 2 * S_BYTES;

    __shared__ float4 As_s[NN], Bs_s[NN];
    __shared__ float4 den_part[8][64];

    const int t = threadIdx.x;
    const int lane = t & 31, w = t >> 5;
    const int b  = blockIdx.x >> 4;
    const int i0 = (blockIdx.x & 15) << 6;

    const char* hsrc = (const char*)g_hh + ((size_t)(b << 10) << 9);
    #pragma unroll
    for (int kc = 0; kc < 2; ++kc) {
        #pragma unroll
        for (int l = 0; l < 4; ++l) {
            int idx = t + (l << 9);
            CP_ASYNC16(sbH + kc * HTILE + (idx >> 5) * HROW + ((idx & 31) << 4),
                       hsrc + (size_t)kc * (64 * 512) + ((size_t)idx << 4));
        }
        CP_COMMIT();
    }

    for (int k = t; k < NN; k += 512) {
        float4 sd = ((const float4*)g_sdst)[(b << 10) + k];
        As_s[k] = make_float4(__expf(sd.x), __expf(sd.y), __expf(sd.z), __expf(sd.w));
        Bs_s[k] = make_float4(__expf(NEG_SLOPE * sd.x), __expf(NEG_SLOPE * sd.y),
                              __expf(NEG_SLOPE * sd.z), __expf(NEG_SLOPE * sd.w));
    }

    const int iw = t & 63;
    const int jc = t >> 6;
    float4 P4, Q4, R4;
    {
        float4 ss = ((const float4*)g_ssrc)[(b << 10) + i0 + iw];
        float4 mx = ((const float4*)g_mx)[b];
        float4 M;
        M.x = ss.x + mx.x; M.x = fmaxf(M.x, NEG_SLOPE * M.x);
        M.y = ss.y + mx.y; M.y = fmaxf(M.y, NEG_SLOPE * M.y);
        M.z = ss.z + mx.z; M.z = fmaxf(M.z, NEG_SLOPE * M.z);
        M.w = ss.w + mx.w; M.w = fmaxf(M.w, NEG_SLOPE * M.w);
        P4 = make_float4(__expf(ss.x - M.x), __expf(ss.y - M.y),
                         __expf(ss.z - M.z), __expf(ss.w - M.w));
        Q4 = make_float4(__expf(NEG_SLOPE * ss.x - M.x), __expf(NEG_SLOPE * ss.y - M.y),
                         __expf(NEG_SLOPE * ss.z - M.z), __expf(NEG_SLOPE * ss.w - M.w));
        R4 = make_float4(__expf(-ss.x), __expf(-ss.y), __expf(-ss.z), __expf(-ss.w));
    }
    const int4* arow = (const int4*)(adj + (((size_t)(b << 10) + i0 + iw) << 10));
    float d0 = 0.f, d1 = 0.f, d2 = 0.f, d3 = 0.f;

    const int hg = w >> 2, mh = (w >> 1) & 1, nc = w & 1;
    const uint32_t aBase = sbS + hg * SHEAD + ((mh << 5) + (lane & 15)) * SROW
                         + ((lane >> 4) << 4);
    const uint32_t bBase = sbH + (lane & 15) * HROW + ((lane >> 4) << 4)
                         + (hg << 7) + (nc << 6);

    float acc[2][4][4];
    #pragma unroll
    for (int mi = 0; mi < 2; ++mi)
        #pragma unroll
        for (int f = 0; f < 4; ++f)
            #pragma unroll
            for (int c = 0; c < 4; ++c) acc[mi][f][c] = 0.f;

    __syncthreads();

    {
        const int4 m0 = arow[jc << 1];
        const int4 m1 = arow[(jc << 1) + 1];
        const int mvi[8] = { m0.x, m0.y, m0.z, m0.w, m1.x, m1.y, m1.z, m1.w };
        uint32_t pk[4][4];
        float wl[4];
        #pragma unroll
        for (int pp = 0; pp < 8; ++pp) {
            int jl = (jc << 3) + pp;
            float4 A4 = As_s[jl];
            float4 B4 = Bs_s[jl];
            float msk = (mvi[pp] > 0) ? 1.f : 0.f;
            float w0 = msk * ((A4.x > R4.x) ? P4.x * A4.x : Q4.x * B4.x);
            float w1 = msk * ((A4.y > R4.y) ? P4.y * A4.y : Q4.y * B4.y);
            float w2 = msk * ((A4.z > R4.z) ? P4.z * A4.z : Q4.z * B4.z);
            float w3 = msk * ((A4.w > R4.w) ? P4.w * A4.w : Q4.w * B4.w);
            d0 += w0; d1 += w1; d2 += w2; d3 += w3;
            if (pp & 1) {
                __half2 p0 = __floats2half2_rn(wl[0], w0);
                __half2 p1 = __floats2half2_rn(wl[1], w1);
                __half2 p2 = __floats2half2_rn(wl[2], w2);
                __half2 p3 = __floats2half2_rn(wl[3], w3);
                pk[0][pp >> 1] = *(uint32_t*)&p0;
                pk[1][pp >> 1] = *(uint32_t*)&p1;
                pk[2][pp >> 1] = *(uint32_t*)&p2;
                pk[3][pp >> 1] = *(uint32_t*)&p3;
            } else { wl[0] = w0; wl[1] = w1; wl[2] = w2; wl[3] = w3; }
        }
        const uint32_t base = sbS + iw * SROW + (jc << 4);
        #pragma unroll
        for (int hh = 0; hh < 4; ++hh)
            asm volatile("st.shared.v4.b32 [%0], {%1,%2,%3,%4};"
                :: "r"(base + hh * SHEAD),
                   "r"(pk[hh][0]), "r"(pk[hh][1]), "r"(pk[hh][2]), "r"(pk[hh][3]) : "memory");
    }
    CP_WAIT1();
    __syncthreads();

    for (int jt = 0; jt < 16; ++jt) {
        if (jt + 2 < 16) {
            const char* src = hsrc + (size_t)(jt + 2) * (64 * 512);
            const uint32_t dst = sbH + ((jt + 2) % 3) * HTILE;
            #pragma unroll
            for (int l = 0; l < 4; ++l) {
                int idx = t + (l << 9);
                CP_ASYNC16(dst + (idx >> 5) * HROW + ((idx & 31) << 4),
                           src + ((size_t)idx << 4));
            }
            CP_COMMIT();
        }

        {
            const uint32_t aB = aBase + (jt & 1) * S_BYTES;
            const uint32_t bB = bBase + (jt % 3) * HTILE;
            #pragma unroll
            for (int ks = 0; ks < 4; ++ks) {
                uint32_t Af[2][4];
                ldsm_x4(Af[0], aB + (ks << 5));
                ldsm_x4(Af[1], aB + 16 * SROW + (ks << 5));
                #pragma unroll
                for (int nn = 0; nn < 2; ++nn) {
                    uint32_t Bf[4];
                    ldsm_x4t(Bf, bB + ks * (16 * HROW) + (nn << 5));
                    mma16816(acc[0][2 * nn],     Af[0], Bf[0], Bf[1]);
                    mma16816(acc[0][2 * nn + 1], Af[0], Bf[2], Bf[3]);
                    mma16816(acc[1][2 * nn],     Af[1], Bf[0], Bf[1]);
                    mma16816(acc[1][2 * nn + 1], Af[1], Bf[2], Bf[3]);
                }
            }
        }
        if (jt == 15) break;

        {
            const int jn = jt + 1;
            const int j0 = jn << 6;
            const int4 m0 = arow[(jn << 4) + (jc << 1)];
            const int4 m1 = arow[(jn << 4) + (jc << 1) + 1];
            const int mvi[8] = { m0.x, m0.y, m0.z, m0.w, m1.x, m1.y, m1.z, m1.w };
            uint32_t pk[4][4];
            float wl[4];
            #pragma unroll
            for (int pp = 0; pp < 8; ++pp) {
                int jl = (jc << 3) + pp;
                float4 A4 = As_s[j0 + jl];
                float4 B4 = Bs_s[j0 + jl];
                float msk = (mvi[pp] > 0) ? 1.f : 0.f;
                float w0 = msk * ((A4.x > R4.x) ? P4.x * A4.x : Q4.x * B4.x);
                float w1 = msk * ((A4.y > R4.y) ? P4.y * A4.y : Q4.y * B4.y);
                float w2 = msk * ((A4.z > R4.z) ? P4.z * A4.z : Q4.z * B4.z);
                float w3 = msk * ((A4.w > R4.w) ? P4.w * A4.w : Q4.w * B4.w);
                d0 += w0; d1 += w1; d2 += w2; d3 += w3;
                if (pp & 1) {
                    __half2 p0 = __floats2half2_rn(wl[0], w0);
                    __half2 p1 = __floats2half2_rn(wl[1], w1);
                    __half2 p2 = __floats2half2_rn(wl[2], w2);
                    __half2 p3 = __floats2half2_rn(wl[3], w3);
                    pk[0][pp >> 1] = *(uint32_t*)&p0;
                    pk[1][pp >> 1] = *(uint32_t*)&p1;
                    pk[2][pp >> 1] = *(uint32_t*)&p2;
                    pk[3][pp >> 1] = *(uint32_t*)&p3;
                } else { wl[0] = w0; wl[1] = w1; wl[2] = w2; wl[3] = w3; }
            }
            const uint32_t base = sbS + ((jn & 1) ? S_BYTES : 0) + iw * SROW + (jc << 4);
            #pragma unroll
            for (int hh = 0; hh < 4; ++hh)
                asm volatile("st.shared.v4.b32 [%0], {%1,%2,%3,%4};"
                    :: "r"(base + hh * SHEAD),
                       "r"(pk[hh][0]), "r"(pk[hh][1]), "r"(pk[hh][2]), "r"(pk[hh][3]) : "memory");
        }

        if (jt + 2 < 16) { CP_WAIT1(); } else { CP_WAIT0(); }
        __syncthreads();
    }

    den_part[jc][iw] = make_float4(d0, d1, d2, d3);
    __syncthreads();
    if (t < 64) {
        float4 s0 = den_part[0][t];
        #pragma unroll
        for (int q = 1; q < 8; ++q) {
            float4 v = den_part[q][t];
            s0.x += v.x; s0.y += v.y; s0.z += v.z; s0.w += v.w;
        }
        den_part[0][t] = s0;
    }
    __syncthreads();

    const float* denf = (const float*)&den_part[0][0];
    #pragma unroll
    for (int mi = 0; mi < 2; ++mi) {
        const int row_lo = (mh << 5) + (mi << 4) + (lane >> 2);
        float dv0 = 1.f / denf[row_lo * 4 + hg];
        float dv1 = 1.f / denf[(row_lo + 8) * 4 + hg];
        #pragma unroll
        for (int f = 0; f < 4; ++f) {
            int col = (hg << 6) + (nc << 5) + (f << 3) + ((lane & 3) << 1);
            *(float2*)(out + ((b << 10) + i0 + row_lo) * 256 + col) =
                make_float2(acc[mi][f][0] * dv0, acc[mi][f][1] * dv0);
            *(float2*)(out + ((b << 10) + i0 + row_lo + 8) * 256 + col) =
                make_float2(acc[mi][f][2] * dv1, acc[mi][f][3] * dv1);
        }
    }
}

// ============================================================
extern "C" void kernel_launch(void* const* d_in, const int* in_sizes, int n_in,
                              void* d_out, int out_size)
{
    cudaFuncSetAttribute(attn_mma_kernel, cudaFuncAttributeMaxDynamicSharedMemorySize, DYN_BYTES);
    cudaFuncSetAttribute(hgemm_kernel, cudaFuncAttributeMaxDynamicSharedMemorySize, GEMM_DYN);

    const float* x = nullptr; const int* adj = nullptr;
    const float* W = nullptr; const float* a = nullptr;
    for (int i = 0; i < n_in; ++i) {
        int s = in_sizes[i];
        if      (s == BB * NN * INF) x   = (const float*)d_in[i];
        else if (s == BB * NN * NN)  adj = (const int*)d_in[i];
        else if (s == INF * HH * 64) W   = (const float*)d_in[i];
        else if (s == 2 * 64 * HH)   a   = (const float*)d_in[i];
    }

    cvt_kernel<<<4160, 256>>>(x, W);                                   // idx 0
    hgemm_kernel<<<dim3(2, 128), 256, GEMM_DYN>>>(a);                  // idx 1 (h + scores + max)
    attn_mma_kernel<<<BB * (NN / 64), 512, DYN_BYTES>>>(adj, (float*)d_out);  // idx 2
}

// round 17
// speedup vs baseline: 1.4331x; 1.0635x over previous
#include <cuda_runtime.h>
#include <cuda_fp16.h>
#include <cstdint>

#define BB   16
#define NN   1024
#define INF  256
#define HH   4
#define NEG_SLOPE 0.2f

// attn smem: i-tile 64, j-tile 64; S double-buffered, H triple-buffered
#define SROW   144
#define SHEAD  (64 * SROW)        // 9216
#define S_BYTES (4 * SHEAD)       // 36864 per S buffer
#define HROW   528
#define HTILE  (64 * HROW)        // 33792 per H buffer
#define DYN_BYTES (2 * S_BYTES + 3 * HTILE)   // 175104

// hgemm smem: 128m x 128n block, k-chunk 64, double buffered
#define AROWG  144
#define ABUF   (128 * AROWG)
#define BROWG  272
#define BBUF   (64 * BROWG)
#define GEMM_DYN (2 * (ABUF + BBUF))   // 71680

// named barriers (0 reserved for __syncthreads)
#define BARF0 1
#define BARF1 2
#define BARE0 3
#define BARE1 4

// ---- scratch ----
__device__ __half g_xh[BB * NN * 256];
__device__ __half g_Wh[256 * 256];
__device__ __half g_hh[BB * NN * 256];
__device__ float  g_ssrc[BB * NN * HH];
__device__ float  g_sdst[BB * NN * HH];
#define NEG16 -1e30f,-1e30f,-1e30f,-1e30f,-1e30f,-1e30f,-1e30f,-1e30f,\
              -1e30f,-1e30f,-1e30f,-1e30f,-1e30f,-1e30f,-1e30f,-1e30f
__device__ float  g_mx[BB * HH] = { NEG16, NEG16, NEG16, NEG16 };

// ---- helpers ----
__device__ __forceinline__ uint32_t smem_u32(const void* p) {
    uint32_t a;
    asm("{ .reg .u64 t; cvta.to.shared.u64 t, %1; cvt.u32.u64 %0, t; }" : "=r"(a) : "l"(p));
    return a;
}
__device__ __forceinline__ void ldsm_x4(uint32_t* d, uint32_t addr) {
    asm volatile("ldmatrix.sync.aligned.m8n8.x4.shared.b16 {%0,%1,%2,%3}, [%4];"
        : "=r"(d[0]), "=r"(d[1]), "=r"(d[2]), "=r"(d[3]) : "r"(addr));
}
__device__ __forceinline__ void ldsm_x4t(uint32_t* d, uint32_t addr) {
    asm volatile("ldmatrix.sync.aligned.m8n8.x4.trans.shared.b16 {%0,%1,%2,%3}, [%4];"
        : "=r"(d[0]), "=r"(d[1]), "=r"(d[2]), "=r"(d[3]) : "r"(addr));
}
__device__ __forceinline__ void mma16816(float* c, const uint32_t* a, uint32_t b0, uint32_t b1) {
    asm volatile("mma.sync.aligned.m16n8k16.row.col.f32.f16.f16.f32 "
        "{%0,%1,%2,%3}, {%4,%5,%6,%7}, {%8,%9}, {%0,%1,%2,%3};"
        : "+f"(c[0]), "+f"(c[1]), "+f"(c[2]), "+f"(c[3])
        : "r"(a[0]), "r"(a[1]), "r"(a[2]), "r"(a[3]), "r"(b0), "r"(b1));
}
#define CP_ASYNC16(smem, gptr) \
    asm volatile("cp.async.cg.shared.global [%0], [%1], 16;" :: "r"(smem), "l"(gptr) : "memory")
#define CP_COMMIT() asm volatile("cp.async.commit_group;" ::: "memory")
#define CP_WAIT1()  asm volatile("cp.async.wait_group 1;" ::: "memory")
#define CP_WAIT0()  asm volatile("cp.async.wait_group 0;" ::: "memory")
#define BAR_SYNC(id)   asm volatile("bar.sync %0, 512;"   :: "r"(id) : "memory")
#define BAR_ARRIVE(id) asm volatile("bar.arrive %0, 512;" :: "r"(id) : "memory")
#define MEMBAR_CTA()   asm volatile("membar.cta;" ::: "memory")

__device__ __forceinline__ void atomicMaxFloat(float* a, float v) {
    if (v >= 0.f) atomicMax((int*)a, __float_as_int(v));
    else          atomicMin((unsigned int*)a, __float_as_uint(v));
}

// ============================================================
// [0] fused fp32->fp16 convert: x + W
// ============================================================
__global__ __launch_bounds__(256) void cvt_kernel(const float* __restrict__ x,
                                                  const float* __restrict__ W)
{
    int id = blockIdx.x * 256 + threadIdx.x;
    int i  = id << 2;
    const float* src;
    unsigned short* dst;
    if (i < BB * NN * 256) { src = x + i; dst = (unsigned short*)g_xh + i; }
    else { i -= BB * NN * 256; src = W + i; dst = (unsigned short*)g_Wh + i; }
    float4 v = *(const float4*)src;
    __half2 h0 = __floats2half2_rn(v.x, v.y);
    __half2 h1 = __floats2half2_rn(v.z, v.w);
    *(uint2*)dst = make_uint2(*(uint32_t*)&h0, *(uint32_t*)&h1);
}

// ============================================================
// [1] h = x @ W via HMMA -> g_hh + fused scores (unchanged from r16)
// ============================================================
__global__ __launch_bounds__(256, 1)
void hgemm_kernel(const float* __restrict__ av)
{
    extern __shared__ __align__(16) char sg[];
    const uint32_t sbA = smem_u32(sg);
    const uint32_t sbB = sbA + 2 * ABUF;
    __shared__ float av_s[512];

    const int t = threadIdx.x;
    const int lane = t & 31, w = t >> 5;
    const int nBase = blockIdx.x << 7;
    const int mBase = blockIdx.y << 7;

    const char* aSrc = (const char*)g_xh + (size_t)mBase * 512;
    const char* bSrc = (const char*)g_Wh + (size_t)nBase * 2;

    #pragma unroll
    for (int kc = 0; kc < 2; ++kc) {
        #pragma unroll
        for (int l = 0; l < 4; ++l) {
            int idx = t + (l << 8);
            CP_ASYNC16(sbA + kc * ABUF + (idx >> 3) * AROWG + ((idx & 7) << 4),
                       aSrc + (size_t)(idx >> 3) * 512 + kc * 128 + ((idx & 7) << 4));
        }
        #pragma unroll
        for (int l = 0; l < 4; ++l) {
            int idx = t + (l << 8);
            CP_ASYNC16(sbB + kc * BBUF + (idx >> 4) * BROWG + ((idx & 15) << 4),
                       bSrc + (size_t)(kc * 64 + (idx >> 4)) * 512 + ((idx & 15) << 4));
        }
        CP_COMMIT();
    }
    av_s[t] = av[t];
    av_s[256 + t] = av[256 + t];

    const int mw = w & 3, nw = w >> 2;
    const uint32_t aBase = sbA + ((mw << 5) + (lane & 15)) * AROWG + ((lane >> 4) << 4);
    const uint32_t bBase = sbB + (lane & 15) * BROWG + ((lane >> 4) << 4) + (nw << 7);

    float acc[2][8][4];
    #pragma unroll
    for (int f = 0; f < 2; ++f)
        #pragma unroll
        for (int n = 0; n < 8; ++n)
            #pragma unroll
            for (int c = 0; c < 4; ++c) acc[f][n][c] = 0.f;

    for (int kc = 0; kc < 4; ++kc) {
        if (kc + 2 < 4) { CP_WAIT1(); } else { CP_WAIT0(); }
        __syncthreads();
        const uint32_t aB = aBase + (kc & 1) * ABUF;
        const uint32_t bB = bBase + (kc & 1) * BBUF;
        #pragma unroll
        for (int ks = 0; ks < 4; ++ks) {
            uint32_t Af[2][4];
            ldsm_x4(Af[0], aB + (ks << 5));
            ldsm_x4(Af[1], aB + 16 * AROWG + (ks << 5));
            #pragma unroll
            for (int nn = 0; nn < 4; ++nn) {
                uint32_t Bf[4];
                ldsm_x4t(Bf, bB + ks * (16 * BROWG) + (nn << 5));
                mma16816(acc[0][2 * nn],     Af[0], Bf[0], Bf[1]);
                mma16816(acc[0][2 * nn + 1], Af[0], Bf[2], Bf[3]);
                mma16816(acc[1][2 * nn],     Af[1], Bf[0], Bf[1]);
                mma16816(acc[1][2 * nn + 1], Af[1], Bf[2], Bf[3]);
            }
        }
        __syncthreads();
        if (kc + 2 < 4) {
            int kn = kc + 2;
            #pragma unroll
            for (int l = 0; l < 4; ++l) {
                int idx = t + (l << 8);
                CP_ASYNC16(sbA + (kc & 1) * ABUF + (idx >> 3) * AROWG + ((idx & 7) << 4),
                           aSrc + (size_t)(idx >> 3) * 512 + kn * 128 + ((idx & 7) << 4));
            }
            #pragma unroll
            for (int l = 0; l < 4; ++l) {
                int idx = t + (l << 8);
                CP_ASYNC16(sbB + (kc & 1) * BBUF + (idx >> 4) * BROWG + ((idx & 15) << 4),
                           bSrc + (size_t)(kn * 64 + (idx >> 4)) * 512 + ((idx & 15) << 4));
            }
            CP_COMMIT();
        }
    }

    #pragma unroll
    for (int f = 0; f < 2; ++f) {
        int row0 = mBase + (mw << 5) + (f << 4) + (lane >> 2);
        #pragma unroll
        for (int n = 0; n < 8; ++n) {
            int col = nBase + (nw << 6) + (n << 3) + ((lane & 3) << 1);
            __half2 lo = __floats2half2_rn(acc[f][n][0], acc[f][n][1]);
            __half2 hi = __floats2half2_rn(acc[f][n][2], acc[f][n][3]);
            *(uint32_t*)((unsigned short*)g_hh + row0 * 256 + col)       = *(uint32_t*)&lo;
            *(uint32_t*)((unsigned short*)g_hh + (row0 + 8) * 256 + col) = *(uint32_t*)&hi;
        }
    }

    const int head = (nBase >> 6) + nw;
    float sc[2][2][2];
    #pragma unroll
    for (int f = 0; f < 2; ++f)
        #pragma unroll
        for (int rh = 0; rh < 2; ++rh) { sc[f][rh][0] = 0.f; sc[f][rh][1] = 0.f; }
    #pragma unroll
    for (int n = 0; n < 8; ++n) {
        int d0 = (n << 3) + ((lane & 3) << 1);
        float as0 = av_s[d0 * 4 + head],        as1 = av_s[(d0 + 1) * 4 + head];
        float ad0 = av_s[(64 + d0) * 4 + head], ad1 = av_s[(64 + d0 + 1) * 4 + head];
        #pragma unroll
        for (int f = 0; f < 2; ++f) {
            sc[f][0][0] += acc[f][n][0] * as0 + acc[f][n][1] * as1;
            sc[f][0][1] += acc[f][n][0] * ad0 + acc[f][n][1] * ad1;
            sc[f][1][0] += acc[f][n][2] * as0 + acc[f][n][3] * as1;
            sc[f][1][1] += acc[f][n][2] * ad0 + acc[f][n][3] * ad1;
        }
    }
    #pragma unroll
    for (int o = 1; o < 4; o <<= 1)
        #pragma unroll
        for (int f = 0; f < 2; ++f)
            #pragma unroll
            for (int rh = 0; rh < 2; ++rh) {
                sc[f][rh][0] += __shfl_xor_sync(0xffffffffu, sc[f][rh][0], o);
                sc[f][rh][1] += __shfl_xor_sync(0xffffffffu, sc[f][rh][1], o);
            }
    if ((lane & 3) == 0) {
        #pragma unroll
        for (int f = 0; f < 2; ++f)
            #pragma unroll
            for (int rh = 0; rh < 2; ++rh) {
                int row = mBase + (mw << 5) + (f << 4) + (lane >> 2) + (rh << 3);
                g_ssrc[row * 4 + head] = sc[f][rh][0];
                g_sdst[row * 4 + head] = sc[f][rh][1];
                atomicMaxFloat(&g_mx[(row >> 10) * 4 + head], sc[f][rh][1]);
            }
    }
}

// ============================================================
// [2] warp-specialized HMMA attention aggregation.
//     512 thr: warps 0-7 = MMA consumers (warp = head hg x n32 nc, m64,
//     acc[4][4][4]); warps 8-15 = weight producers (thread = row iw x
//     16-j chunk jc) + all H cp.async. Named-barrier handoff:
//     F[b]: producers arrive (post-membar), consumers sync.
//     E[b]: consumers arrive, producers sync. S x2, H x3.
// ============================================================
__global__ __launch_bounds__(512, 1)
void attn_mma_kernel(const int* __restrict__ adj, float* __restrict__ out)
{
    extern __shared__ __align__(16) char sb[];
    const uint32_t sbS = smem_u32(sb);
    const uint32_t sbH = sbS + 2 * S_BYTES;

    __shared__ float4 As_s[NN], Bs_s[NN];          // 32 KB
    __shared__ float4 den_part[4][64];             // 4 KB

    const int t = threadIdx.x;
    const int lane = t & 31, w = t >> 5;
    const int b  = blockIdx.x >> 4;
    const int i0 = (blockIdx.x & 15) << 6;

    // all threads: eA/eB prep
    for (int k = t; k < NN; k += 512) {
        float4 sd = ((const float4*)g_sdst)[(b << 10) + k];
        As_s[k] = make_float4(__expf(sd.x), __expf(sd.y), __expf(sd.z), __expf(sd.w));
        Bs_s[k] = make_float4(__expf(NEG_SLOPE * sd.x), __expf(NEG_SLOPE * sd.y),
                              __expf(NEG_SLOPE * sd.z), __expf(NEG_SLOPE * sd.w));
    }
    __syncthreads();

    const char* hsrc = (const char*)g_hh + ((size_t)(b << 10) << 9);

    if (w >= 8) {
        // ================= PRODUCER =================
        const int pt = t - 256;
        const int iw = pt & 63;
        const int jc = pt >> 6;                    // 16-j chunk (0..3)
        float4 P4, Q4, R4;
        {
            float4 ss = ((const float4*)g_ssrc)[(b << 10) + i0 + iw];
            float4 mx = ((const float4*)g_mx)[b];
            float4 M;
            M.x = ss.x + mx.x; M.x = fmaxf(M.x, NEG_SLOPE * M.x);
            M.y = ss.y + mx.y; M.y = fmaxf(M.y, NEG_SLOPE * M.y);
            M.z = ss.z + mx.z; M.z = fmaxf(M.z, NEG_SLOPE * M.z);
            M.w = ss.w + mx.w; M.w = fmaxf(M.w, NEG_SLOPE * M.w);
            P4 = make_float4(__expf(ss.x - M.x), __expf(ss.y - M.y),
                             __expf(ss.z - M.z), __expf(ss.w - M.w));
            Q4 = make_float4(__expf(NEG_SLOPE * ss.x - M.x), __expf(NEG_SLOPE * ss.y - M.y),
                             __expf(NEG_SLOPE * ss.z - M.z), __expf(NEG_SLOPE * ss.w - M.w));
            R4 = make_float4(__expf(-ss.x), __expf(-ss.y), __expf(-ss.z), __expf(-ss.w));
        }
        const int4* arow = (const int4*)(adj + (((size_t)(b << 10) + i0 + iw) << 10) + (jc << 4));
        float d0 = 0.f, d1 = 0.f, d2 = 0.f, d3 = 0.f;

        // H prefetch lambda-ish macro body (8x16B per producer thread)
        #define PROD_H(jn, buf) do { \
            const char* _src = hsrc + (size_t)(jn) * (64 * 512); \
            const uint32_t _dst = sbH + (buf) * HTILE; \
            _Pragma("unroll") \
            for (int l = 0; l < 8; ++l) { \
                int idx = pt + (l << 8); \
                CP_ASYNC16(_dst + (idx >> 5) * HROW + ((idx & 31) << 4), \
                           _src + ((size_t)idx << 4)); \
            } \
            CP_COMMIT(); \
        } while (0)

        #define PROD_S(jn, sbuf) do { \
            const int4 mv[4] = { arow[((jn) << 4) + 0], arow[((jn) << 4) + 1], \
                                 arow[((jn) << 4) + 2], arow[((jn) << 4) + 3] }; \
            const int* mvi = (const int*)mv; \
            const int j0 = (jn) << 6; \
            _Pragma("unroll") \
            for (int gHalf = 0; gHalf < 2; ++gHalf) { \
                uint32_t pk[4][4]; \
                float wl[4]; \
                _Pragma("unroll") \
                for (int pp = 0; pp < 8; ++pp) { \
                    int jl = (jc << 4) + (gHalf << 3) + pp; \
                    float4 A4 = As_s[j0 + jl]; \
                    float4 B4 = Bs_s[j0 + jl]; \
                    float msk = (mvi[(gHalf << 3) + pp] > 0) ? 1.f : 0.f; \
                    float w0 = msk * ((A4.x > R4.x) ? P4.x * A4.x : Q4.x * B4.x); \
                    float w1 = msk * ((A4.y > R4.y) ? P4.y * A4.y : Q4.y * B4.y); \
                    float w2 = msk * ((A4.z > R4.z) ? P4.z * A4.z : Q4.z * B4.z); \
                    float w3 = msk * ((A4.w > R4.w) ? P4.w * A4.w : Q4.w * B4.w); \
                    d0 += w0; d1 += w1; d2 += w2; d3 += w3; \
                    if (pp & 1) { \
                        __half2 p0 = __floats2half2_rn(wl[0], w0); \
                        __half2 p1 = __floats2half2_rn(wl[1], w1); \
                        __half2 p2 = __floats2half2_rn(wl[2], w2); \
                        __half2 p3 = __floats2half2_rn(wl[3], w3); \
                        pk[0][pp >> 1] = *(uint32_t*)&p0; \
                        pk[1][pp >> 1] = *(uint32_t*)&p1; \
                        pk[2][pp >> 1] = *(uint32_t*)&p2; \
                        pk[3][pp >> 1] = *(uint32_t*)&p3; \
                    } else { wl[0] = w0; wl[1] = w1; wl[2] = w2; wl[3] = w3; } \
                } \
                const uint32_t base = sbS + (sbuf) * S_BYTES + iw * SROW + (jc << 5) + (gHalf << 4); \
                _Pragma("unroll") \
                for (int hh = 0; hh < 4; ++hh) \
                    asm volatile("st.shared.v4.b32 [%0], {%1,%2,%3,%4};" \
                        :: "r"(base + hh * SHEAD), \
                           "r"(pk[hh][0]), "r"(pk[hh][1]), "r"(pk[hh][2]), "r"(pk[hh][3]) : "memory"); \
            } \
        } while (0)

        PROD_H(0, 0);
        PROD_H(1, 1);
        PROD_S(0, 0);
        CP_WAIT1();                                // H(0) done
        MEMBAR_CTA();
        BAR_ARRIVE(BARF0);

        PROD_H(2, 2);
        PROD_S(1, 1);
        CP_WAIT1();                                // H(1) done
        MEMBAR_CTA();
        BAR_ARRIVE(BARF1);

        for (int jt = 2; jt < 16; ++jt) {
            if (jt & 1) BAR_SYNC(BARE1); else BAR_SYNC(BARE0);
            if (jt + 1 < 16) PROD_H(jt + 1, (jt + 1) % 3);
            PROD_S(jt, jt & 1);
            if (jt + 1 < 16) { CP_WAIT1(); } else { CP_WAIT0(); }   // H(jt) done
            MEMBAR_CTA();
            if (jt & 1) BAR_ARRIVE(BARF1); else BAR_ARRIVE(BARF0);
        }
        den_part[jc][iw] = make_float4(d0, d1, d2, d3);
    } else {
        // ================= CONSUMER =================
        const int hg = w >> 1, nc = w & 1;
        const uint32_t aBase = sbS + hg * SHEAD + (lane & 15) * SROW + ((lane >> 4) << 4);
        const uint32_t bBase = sbH + (lane & 15) * HROW + ((lane >> 4) << 4)
                             + (hg << 7) + (nc << 6);

        float acc[4][4][4];
        #pragma unroll
        for (int mi = 0; mi < 4; ++mi)
            #pragma unroll
            for (int f = 0; f < 4; ++f)
                #pragma unroll
                for (int c = 0; c < 4; ++c) acc[mi][f][c] = 0.f;

        for (int jt = 0; jt < 16; ++jt) {
            if (jt & 1) BAR_SYNC(BARF1); else BAR_SYNC(BARF0);
            const uint32_t aB = aBase + (jt & 1) * S_BYTES;
            const uint32_t bB = bBase + (jt % 3) * HTILE;
            #pragma unroll
            for (int ks = 0; ks < 4; ++ks) {
                uint32_t Af[4][4];
                #pragma unroll
                for (int mi = 0; mi < 4; ++mi)
                    ldsm_x4(Af[mi], aB + mi * (16 * SROW) + (ks << 5));
                #pragma unroll
                for (int nn = 0; nn < 2; ++nn) {
                    uint32_t Bf[4];
                    ldsm_x4t(Bf, bB + ks * (16 * HROW) + (nn << 5));
                    #pragma unroll
                    for (int mi = 0; mi < 4; ++mi) {
                        mma16816(acc[mi][2 * nn],     Af[mi], Bf[0], Bf[1]);
                        mma16816(acc[mi][2 * nn + 1], Af[mi], Bf[2], Bf[3]);
                    }
                }
            }
            if (jt <= 13) {
                if (jt & 1) BAR_ARRIVE(BARE1); else BAR_ARRIVE(BARE0);
            }
        }

        __syncthreads();                           // producers wrote den_part (see below)
        const float* denf = (const float*)&den_part[0][0];
        #pragma unroll
        for (int mi = 0; mi < 4; ++mi) {
            const int row_lo = (mi << 4) + (lane >> 2);
            float den0 = 0.f, den1 = 0.f;
            #pragma unroll
            for (int q = 0; q < 4; ++q) {
                den0 += denf[(q * 64 + row_lo) * 4 + hg];
                den1 += denf[(q * 64 + row_lo + 8) * 4 + hg];
            }
            float dv0 = 1.f / den0;
            float dv1 = 1.f / den1;
            #pragma unroll
            for (int f = 0; f < 4; ++f) {
                int col = (hg << 6) + (nc << 5) + (f << 3) + ((lane & 3) << 1);
                *(float2*)(out + ((b << 10) + i0 + row_lo) * 256 + col) =
                    make_float2(acc[mi][f][0] * dv0, acc[mi][f][1] * dv0);
                *(float2*)(out + ((b << 10) + i0 + row_lo + 8) * 256 + col) =
                    make_float2(acc[mi][f][2] * dv1, acc[mi][f][3] * dv1);
            }
        }
        return;
    }
    __syncthreads();                               // producer side: release den_part
}

// ============================================================
extern "C" void kernel_launch(void* const* d_in, const int* in_sizes, int n_in,
                              void* d_out, int out_size)
{
    cudaFuncSetAttribute(attn_mma_kernel, cudaFuncAttributeMaxDynamicSharedMemorySize, DYN_BYTES);
    cudaFuncSetAttribute(hgemm_kernel, cudaFuncAttributeMaxDynamicSharedMemorySize, GEMM_DYN);

    const float* x = nullptr; const int* adj = nullptr;
    const float* W = nullptr; const float* a = nullptr;
    for (int i = 0; i < n_in; ++i) {
        int s = in_sizes[i];
        if      (s == BB * NN * INF) x   = (const float*)d_in[i];
        else if (s == BB * NN * NN)  adj = (const int*)d_in[i];
        else if (s == INF * HH * 64) W   = (const float*)d_in[i];
        else if (s == 2 * 64 * HH)   a   = (const float*)d_in[i];
    }

    cvt_kernel<<<4160, 256>>>(x, W);
    hgemm_kernel<<<dim3(2, 128), 256, GEMM_DYN>>>(a);
    attn_mma_kernel<<<BB * (NN / 64), 512, DYN_BYTES>>>(adj, (float*)d_out);
}